// round 1
// baseline (speedup 1.0000x reference)
#include <cuda_runtime.h>
#include <math.h>

#define NB 8
#define NT 16
#define NL 128
#define NR 1024
#define NE 5
#define NF 512

// scratch (allocation-free rule: __device__ globals)
__device__ float g_atn[(size_t)NB * NE * NL * NR];   // [b][e][l][r]  ~21 MB
__device__ float g_newlig[NB * NT * NL * 3];          // [b][t][l][xyz]

// ---------------------------------------------------------------------------
// Kernel 1: Householder QR (LAPACK convention) + rotate/translate lig coords.
// grid = B*T blocks, NL threads. Also zero-inits out[bt].
// ---------------------------------------------------------------------------
__global__ void rot_kernel(const float* __restrict__ pre_rot,
                           const float* __restrict__ lig_coord,
                           const float* __restrict__ trans,
                           float* __restrict__ out) {
    int bt = blockIdx.x;            // b*NT + t
    int b = bt / NT;
    if (threadIdx.x == 0) out[bt] = 0.f;

    const float* A0 = pre_rot + bt * 9;
    float a00 = A0[0], a01 = A0[1], a02 = A0[2];
    float a10 = A0[3], a11 = A0[4], a12 = A0[5];
    float a20 = A0[6], a21 = A0[7], a22 = A0[8];

    // --- reflector 0 on column 0 (LAPACK slarfg convention) ---
    float v1 = 0.f, v2 = 0.f, tau0 = 0.f;
    float xn2 = a10 * a10 + a20 * a20;
    if (xn2 > 0.f) {
        float beta = -copysignf(sqrtf(a00 * a00 + xn2), a00);
        tau0 = (beta - a00) / beta;
        float inv = 1.f / (a00 - beta);
        v1 = a10 * inv;
        v2 = a20 * inv;
        // apply H0 = I - tau0*u u^T, u=(1,v1,v2) to trailing columns 1,2
        float w1 = a01 + v1 * a11 + v2 * a21;
        a01 -= tau0 * w1; a11 -= tau0 * v1 * w1; a21 -= tau0 * v2 * w1;
        float w2 = a02 + v1 * a12 + v2 * a22;
        a02 -= tau0 * w2; a12 -= tau0 * v1 * w2; a22 -= tau0 * v2 * w2;
    }
    // --- reflector 1 on column 1 rows 1..2 ---
    float u2 = 0.f, tau1 = 0.f;
    if (a21 != 0.f) {
        float beta1 = -copysignf(sqrtf(a11 * a11 + a21 * a21), a11);
        tau1 = (beta1 - a11) / beta1;
        u2 = a21 / (a11 - beta1);
    }

    // Q = H0 * H1
    float H0m[3][3] = {
        {1.f - tau0,      -tau0 * v1,           -tau0 * v2},
        {-tau0 * v1, 1.f - tau0 * v1 * v1,      -tau0 * v1 * v2},
        {-tau0 * v2,      -tau0 * v1 * v2, 1.f - tau0 * v2 * v2}};
    float H1m[3][3] = {
        {1.f, 0.f, 0.f},
        {0.f, 1.f - tau1,      -tau1 * u2},
        {0.f, -tau1 * u2, 1.f - tau1 * u2 * u2}};
    float Q[3][3];
#pragma unroll
    for (int i = 0; i < 3; i++)
#pragma unroll
        for (int j = 0; j < 3; j++)
            Q[i][j] = H0m[i][0] * H1m[0][j] + H0m[i][1] * H1m[1][j] + H0m[i][2] * H1m[2][j];

    int l = threadIdx.x;
    float cx = lig_coord[(b * NL + l) * 3 + 0];
    float cy = lig_coord[(b * NL + l) * 3 + 1];
    float cz = lig_coord[(b * NL + l) * 3 + 2];
    float tx = trans[bt * 3 + 0], ty = trans[bt * 3 + 1], tz = trans[bt * 3 + 2];
    float* o = g_newlig + (bt * NL + l) * 3;
    o[0] = Q[0][0] * cx + Q[0][1] * cy + Q[0][2] * cz + tx;
    o[1] = Q[1][0] * cx + Q[1][1] * cy + Q[1][2] * cz + ty;
    o[2] = Q[2][0] * cx + Q[2][1] * cy + Q[2][2] * cz + tz;
}

// ---------------------------------------------------------------------------
// Kernel 2: atn[b][e][l][r] = sum_f lig[b,l,e,f]*rec[b,r,e,f], masked.
// 40 GEMMs of 128x1024x512. Tile: BM=64, BN=128, BK=16, 256 threads, 4x8/thread.
// grid = (NR/128, NL/64, NB*NE)
// ---------------------------------------------------------------------------
__global__ void __launch_bounds__(256) atn_gemm(const float* __restrict__ lig_feat,
                                                const float* __restrict__ rec_feat,
                                                const int* __restrict__ ligc,
                                                const int* __restrict__ recc) {
    const int be = blockIdx.z;
    const int b = be / NE, e = be % NE;
    const int m0 = blockIdx.y * 64;
    const int n0 = blockIdx.x * 128;
    const int rowstride = NE * NF;   // 2560

    const float* A = lig_feat + (size_t)(b * NL * NE + e) * NF;
    const float* Bp = rec_feat + (size_t)(b * NR * NE + e) * NF;

    __shared__ float As[16][68];
    __shared__ float Bs[16][132];

    const int tid = threadIdx.x;
    const int arow = tid >> 2;            // 0..63
    const int acol = (tid & 3) << 2;      // 0,4,8,12
    const int brow = tid >> 1;            // 0..127
    const int bcol = (tid & 1) << 3;      // 0,8
    const int rtid = tid >> 4;            // 0..15
    const int ctid = tid & 15;            // 0..15

    float acc[4][8];
#pragma unroll
    for (int i = 0; i < 4; i++)
#pragma unroll
        for (int j = 0; j < 8; j++) acc[i][j] = 0.f;

    const float* Aload = A + (size_t)(m0 + arow) * rowstride + acol;
    const float* Bload = Bp + (size_t)(n0 + brow) * rowstride + bcol;

    for (int k0 = 0; k0 < NF; k0 += 16) {
        float4 av  = *(const float4*)(Aload + k0);
        float4 bv0 = *(const float4*)(Bload + k0);
        float4 bv1 = *(const float4*)(Bload + k0 + 4);
        __syncthreads();
        As[acol + 0][arow] = av.x;
        As[acol + 1][arow] = av.y;
        As[acol + 2][arow] = av.z;
        As[acol + 3][arow] = av.w;
        Bs[bcol + 0][brow] = bv0.x;
        Bs[bcol + 1][brow] = bv0.y;
        Bs[bcol + 2][brow] = bv0.z;
        Bs[bcol + 3][brow] = bv0.w;
        Bs[bcol + 4][brow] = bv1.x;
        Bs[bcol + 5][brow] = bv1.y;
        Bs[bcol + 6][brow] = bv1.z;
        Bs[bcol + 7][brow] = bv1.w;
        __syncthreads();
#pragma unroll
        for (int k = 0; k < 16; k++) {
            float4 af = *(const float4*)&As[k][rtid << 2];
            float4 b0 = *(const float4*)&Bs[k][ctid << 2];
            float4 b1 = *(const float4*)&Bs[k][64 + (ctid << 2)];
            float ar[4] = {af.x, af.y, af.z, af.w};
            float br[8] = {b0.x, b0.y, b0.z, b0.w, b1.x, b1.y, b1.z, b1.w};
#pragma unroll
            for (int i = 0; i < 4; i++)
#pragma unroll
                for (int j = 0; j < 8; j++)
                    acc[i][j] = fmaf(ar[i], br[j], acc[i][j]);
        }
    }

    const int lc = __ldg(&ligc[b]);
    const int rc = __ldg(&recc[b]);
    float* C = g_atn + (size_t)(b * NE + e) * NL * NR;
#pragma unroll
    for (int i = 0; i < 4; i++) {
        int l = m0 + (rtid << 2) + i;
        bool lok = l < lc;
#pragma unroll
        for (int g = 0; g < 2; g++) {
            int c0 = n0 + g * 64 + (ctid << 2);
            float4 o;
            o.x = (lok && (c0 + 0) < rc) ? acc[i][g * 4 + 0] : 0.f;
            o.y = (lok && (c0 + 1) < rc) ? acc[i][g * 4 + 1] : 0.f;
            o.z = (lok && (c0 + 2) < rc) ? acc[i][g * 4 + 2] : 0.f;
            o.w = (lok && (c0 + 3) < rc) ? acc[i][g * 4 + 3] : 0.f;
            *(float4*)&C[(size_t)l * NR + c0] = o;
        }
    }
}

// ---------------------------------------------------------------------------
// Kernel 3: U[b,t] += sum_{l,r,e} atn * dist^exp.  exps = [-3,-2,-1,1,2].
// grid = (NL/2, NB), 256 threads. Each block: 2 l-rows x all r, all 16 t.
// ---------------------------------------------------------------------------
__global__ void __launch_bounds__(256) energy_kernel(const float* __restrict__ rec_coord,
                                                     float* __restrict__ out) {
    const int b = blockIdx.y;
    const int l0 = blockIdx.x * 2;
    const int tid = threadIdx.x;

    __shared__ float s_lig[2][NT][3];
    if (tid < 96) {
        int li = tid / 48, rem = tid % 48, t = rem / 3, c = rem % 3;
        s_lig[li][t][c] = g_newlig[((b * NT + t) * NL + (l0 + li)) * 3 + c];
    }
    __syncthreads();

    float acc[NT];
#pragma unroll
    for (int t = 0; t < NT; t++) acc[t] = 0.f;

    const float* rcb = rec_coord + (size_t)b * NR * 3;
    const size_t estride = (size_t)NL * NR;

#pragma unroll
    for (int li = 0; li < 2; li++) {
        const int l = l0 + li;
        const float* atn0 = g_atn + ((size_t)b * NE * NL + l) * NR;
        for (int r = tid; r < NR; r += 256) {
            float a0 = atn0[r];
            float a1 = atn0[estride + r];
            float a2 = atn0[2 * estride + r];
            float a3 = atn0[3 * estride + r];
            float a4 = atn0[4 * estride + r];
            float cx = rcb[r * 3 + 0];
            float cy = rcb[r * 3 + 1];
            float cz = rcb[r * 3 + 2];
#pragma unroll
            for (int t = 0; t < NT; t++) {
                float dx = s_lig[li][t][0] - cx;
                float dy = s_lig[li][t][1] - cy;
                float dz = s_lig[li][t][2] - cz;
                float d2 = fmaf(dx, dx, fmaf(dy, dy, dz * dz));
                d2 = fmaxf(d2, 1e-12f);          // masked pairs: atn==0, keep finite
                float inv = rsqrtf(d2);
                float inv2 = inv * inv;
                float inv3 = inv2 * inv;
                float d = d2 * inv;
                float s = fmaf(a0, inv3, fmaf(a1, inv2, fmaf(a2, inv, fmaf(a3, d, a4 * d2))));
                acc[t] += s;
            }
        }
    }

    // reduce across 256 threads for each t
#pragma unroll
    for (int t = 0; t < NT; t++) {
#pragma unroll
        for (int off = 16; off > 0; off >>= 1)
            acc[t] += __shfl_xor_sync(0xffffffffu, acc[t], off);
    }
    __shared__ float red[8][NT];
    int warp = tid >> 5, lane = tid & 31;
    if (lane == 0) {
#pragma unroll
        for (int t = 0; t < NT; t++) red[warp][t] = acc[t];
    }
    __syncthreads();
    if (tid < NT) {
        float s = 0.f;
#pragma unroll
        for (int w = 0; w < 8; w++) s += red[w][tid];
        atomicAdd(&out[b * NT + tid], s);
    }
}

// ---------------------------------------------------------------------------
extern "C" void kernel_launch(void* const* d_in, const int* in_sizes, int n_in,
                              void* d_out, int out_size) {
    (void)in_sizes; (void)n_in; (void)out_size;
    const float* lig_feat   = (const float*)d_in[0];
    const float* rec_feat   = (const float*)d_in[1];
    const float* lig_coord  = (const float*)d_in[2];
    const float* rec_coord  = (const float*)d_in[3];
    const float* pre_rot    = (const float*)d_in[4];
    const float* trans      = (const float*)d_in[5];
    const int*   lig_counts = (const int*)d_in[6];
    const int*   rec_counts = (const int*)d_in[7];
    float* out = (float*)d_out;

    rot_kernel<<<NB * NT, NL>>>(pre_rot, lig_coord, trans, out);

    dim3 g1(NR / 128, NL / 64, NB * NE);
    atn_gemm<<<g1, 256>>>(lig_feat, rec_feat, lig_counts, rec_counts);

    dim3 g2(NL / 2, NB);
    energy_kernel<<<g2, 256>>>(rec_coord, out);
}

// round 3
// speedup vs baseline: 2.2077x; 2.2077x over previous
#include <cuda_runtime.h>
#include <cuda_bf16.h>
#include <math.h>
#include <stdint.h>

#define NB 8
#define NT 16
#define NL 128
#define NR 1024
#define NE 5
#define NF 512

#define BN 256            // N tile per CTA
#define BK 64             // bf16 K per chunk
#define NCHUNK (NF / BK)  // 8

// tcgen05 is an "a"-feature: only emit it in arch-specific passes.
#if defined(__CUDA_ARCH__) && (defined(__CUDA_ARCH_FEAT_SM103_ALL) || defined(__CUDA_ARCH_FEAT_SM100_ALL))
#define HAS_TC 1
#else
#define HAS_TC 0
#endif

// scratch
__device__ float g_atn[(size_t)NB * NE * NL * NR];   // [b][e][l][r]
__device__ float g_newlig[NB * NT * NL * 3];

// ---------------------------------------------------------------- PTX helpers
__device__ __forceinline__ uint32_t smem_u32(const void* p) {
    uint32_t a;
    asm("{ .reg .u64 t; cvta.to.shared.u64 t, %1; cvt.u32.u64 %0, t; }" : "=r"(a) : "l"(p));
    return a;
}
#if HAS_TC
#define MBAR_INIT(a, n) asm volatile("mbarrier.init.shared.b64 [%0], %1;" :: "r"(a), "r"(n) : "memory")
#define MBAR_ARRIVE(a)  asm volatile("mbarrier.arrive.shared.b64 _, [%0];" :: "r"(a) : "memory")
#define MBAR_WAIT(a, ph) do {                                                     \
    uint32_t _m = (a), _p = (ph), _d;                                             \
    asm volatile("{\n\t.reg .pred p;\n\t"                                         \
        "mbarrier.try_wait.parity.acquire.cta.shared::cta.b64 p, [%1], %2;\n\t"   \
        "selp.b32 %0, 1, 0, p;\n\t}" : "=r"(_d) : "r"(_m), "r"(_p) : "memory");   \
    if (!_d) {                                                                    \
        asm volatile("{\n\t.reg .pred P1;\n\tW%=:\n\t"                            \
            "mbarrier.try_wait.parity.acquire.cta.shared::cta.b64 P1, [%0], %1, 0x989680;\n\t" \
            "@P1 bra.uni D%=;\n\tbra.uni W%=;\n\tD%=:\n\t}"                       \
            :: "r"(_m), "r"(_p) : "memory");                                      \
    }                                                                             \
} while (0)
#define FENCE_ASYNC_SHARED() asm volatile("fence.proxy.async.shared::cta;" ::: "memory")
#define TC_ALLOC(sm_, n)  asm volatile("tcgen05.alloc.cta_group::1.sync.aligned.shared::cta.b32 [%0], %1;" :: "r"(sm_), "r"(n) : "memory")
#define TC_DEALLOC(t, n)  asm volatile("tcgen05.dealloc.cta_group::1.sync.aligned.b32 %0, %1;" :: "r"(t), "r"(n))
#define TC_RELINQ()       asm volatile("tcgen05.relinquish_alloc_permit.cta_group::1.sync.aligned;")
#define TC_COMMIT(mb)     asm volatile("tcgen05.commit.cta_group::1.mbarrier::arrive::one.shared::cluster.b64 [%0];" :: "r"(mb) : "memory")
#define TC_FENCE_AFTER()  asm volatile("tcgen05.fence::after_thread_sync;" ::: "memory")
#define TC_FENCE_BEFORE() asm volatile("tcgen05.fence::before_thread_sync;" ::: "memory")
#define TC_WAIT_LD()      asm volatile("tcgen05.wait::ld.sync.aligned;" ::: "memory")

#define TC_LD_X32(r, ta) \
    asm volatile("tcgen05.ld.sync.aligned.32x32b.x32.b32 " \
        "{%0,%1,%2,%3,%4,%5,%6,%7,%8,%9,%10,%11,%12,%13,%14,%15," \
        "%16,%17,%18,%19,%20,%21,%22,%23,%24,%25,%26,%27,%28,%29,%30,%31}, [%32];" \
        : "=r"((r)[0]),"=r"((r)[1]),"=r"((r)[2]),"=r"((r)[3]),"=r"((r)[4]),"=r"((r)[5]),"=r"((r)[6]),"=r"((r)[7]), \
          "=r"((r)[8]),"=r"((r)[9]),"=r"((r)[10]),"=r"((r)[11]),"=r"((r)[12]),"=r"((r)[13]),"=r"((r)[14]),"=r"((r)[15]), \
          "=r"((r)[16]),"=r"((r)[17]),"=r"((r)[18]),"=r"((r)[19]),"=r"((r)[20]),"=r"((r)[21]),"=r"((r)[22]),"=r"((r)[23]), \
          "=r"((r)[24]),"=r"((r)[25]),"=r"((r)[26]),"=r"((r)[27]),"=r"((r)[28]),"=r"((r)[29]),"=r"((r)[30]),"=r"((r)[31]) \
        : "r"(ta))

// SW128 K-major SMEM descriptor: layout=2, version=1, SBO=64, LBO=1
__device__ __forceinline__ uint64_t make_desc(uint32_t addr) {
    const uint64_t base =
        (uint64_t(2) << 61) | (uint64_t(1) << 46) | (uint64_t(64) << 32) | (uint64_t(1) << 16);
    return base | ((uint64_t)(addr >> 4) & 0x3FFF);
}
// bf16 SS MMA, cta_group::1, fp32 accum
__device__ __forceinline__ void mma_bf16_ss(uint32_t d, uint64_t ad, uint64_t bd,
                                            uint32_t idesc, uint32_t en) {
    asm volatile("{\n\t.reg .pred p;\n\tsetp.ne.u32 p, %4, 0;\n\t"
        "tcgen05.mma.cta_group::1.kind::f16 [%0], %1, %2, %3, {%5,%5,%5,%5}, p;\n\t}"
        :: "r"(d), "l"(ad), "l"(bd), "r"(idesc), "r"(en), "r"(0u) : "memory");
}
#endif  // HAS_TC

// idesc: F32 accum, BF16 a/b, N=256, M=128
#define IDESC ((1u << 4) | (1u << 7) | (1u << 10) | ((BN / 8) << 17) | ((128 / 16) << 24))

// ---------------------------------------------------------------------------
// Kernel 1: Householder QR (LAPACK sign convention) + rigid transform.
// ---------------------------------------------------------------------------
__global__ void rot_kernel(const float* __restrict__ pre_rot,
                           const float* __restrict__ lig_coord,
                           const float* __restrict__ trans,
                           float* __restrict__ out) {
    int bt = blockIdx.x;
    int b = bt / NT;
    if (threadIdx.x == 0) out[bt] = 0.f;

    const float* A0 = pre_rot + bt * 9;
    float a00 = A0[0], a01 = A0[1], a02 = A0[2];
    float a10 = A0[3], a11 = A0[4], a12 = A0[5];
    float a20 = A0[6], a21 = A0[7], a22 = A0[8];

    float v1 = 0.f, v2 = 0.f, tau0 = 0.f;
    float xn2 = a10 * a10 + a20 * a20;
    if (xn2 > 0.f) {
        float beta = -copysignf(sqrtf(a00 * a00 + xn2), a00);
        tau0 = (beta - a00) / beta;
        float inv = 1.f / (a00 - beta);
        v1 = a10 * inv; v2 = a20 * inv;
        float w1 = a01 + v1 * a11 + v2 * a21;
        a01 -= tau0 * w1; a11 -= tau0 * v1 * w1; a21 -= tau0 * v2 * w1;
        float w2 = a02 + v1 * a12 + v2 * a22;
        a02 -= tau0 * w2; a12 -= tau0 * v1 * w2; a22 -= tau0 * v2 * w2;
    }
    float u2 = 0.f, tau1 = 0.f;
    if (a21 != 0.f) {
        float beta1 = -copysignf(sqrtf(a11 * a11 + a21 * a21), a11);
        tau1 = (beta1 - a11) / beta1;
        u2 = a21 / (a11 - beta1);
    }
    float H0m[3][3] = {
        {1.f - tau0, -tau0 * v1, -tau0 * v2},
        {-tau0 * v1, 1.f - tau0 * v1 * v1, -tau0 * v1 * v2},
        {-tau0 * v2, -tau0 * v1 * v2, 1.f - tau0 * v2 * v2}};
    float H1m[3][3] = {
        {1.f, 0.f, 0.f},
        {0.f, 1.f - tau1, -tau1 * u2},
        {0.f, -tau1 * u2, 1.f - tau1 * u2 * u2}};
    float Q[3][3];
#pragma unroll
    for (int i = 0; i < 3; i++)
#pragma unroll
        for (int j = 0; j < 3; j++)
            Q[i][j] = H0m[i][0] * H1m[0][j] + H0m[i][1] * H1m[1][j] + H0m[i][2] * H1m[2][j];

    int l = threadIdx.x;
    float cx = lig_coord[(b * NL + l) * 3 + 0];
    float cy = lig_coord[(b * NL + l) * 3 + 1];
    float cz = lig_coord[(b * NL + l) * 3 + 2];
    float* o = g_newlig + (bt * NL + l) * 3;
    o[0] = Q[0][0] * cx + Q[0][1] * cy + Q[0][2] * cz + trans[bt * 3 + 0];
    o[1] = Q[1][0] * cx + Q[1][1] * cy + Q[1][2] * cz + trans[bt * 3 + 1];
    o[2] = Q[2][0] * cx + Q[2][1] * cy + Q[2][2] * cz + trans[bt * 3 + 2];
}

// ---------------------------------------------------------------------------
// Kernel 2: atn contraction. grid = (4, 40), 256 threads, 197KB dyn smem.
// Fast path: tcgen05 split-bf16 (hi/lo) SS MMA, TMEM fp32 accumulate.
// Fallback path (non-'a' target pass): fp32 SIMT tiled GEMM, same launch cfg.
// ---------------------------------------------------------------------------
#define SM_TMEMP 0
#define SM_FULL0 16
#define SM_FULL1 24
#define SM_EMPTY0 32
#define SM_EMPTY1 40
#define SM_DONE 48
#define STAGE_BYTES 98304
#define AHI_OFF(s) (1024 + (s) * STAGE_BYTES)
#define ALO_OFF(s) (AHI_OFF(s) + 16384)
#define BHI_OFF(s) (AHI_OFF(s) + 32768)
#define BLO_OFF(s) (AHI_OFF(s) + 65536)
#define GEMM_SMEM (1024 + 2 * STAGE_BYTES)

__device__ __forceinline__ uint32_t swz(uint32_t off) { return off ^ ((off >> 3) & 0x70); }
__device__ __forceinline__ uint32_t pack2(__nv_bfloat162 v) {
    return *reinterpret_cast<uint32_t*>(&v);
}

__global__ void __launch_bounds__(256, 1) atn_gemm_tc(const float* __restrict__ lig_feat,
                                                      const float* __restrict__ rec_feat,
                                                      const int* __restrict__ ligc,
                                                      const int* __restrict__ recc) {
    extern __shared__ char sm[];
    const int tid = threadIdx.x;
    const int wid = tid >> 5;
    const int be = blockIdx.y;
    const int b = be / NE, e = be % NE;
    const int n0 = blockIdx.x * BN;
    const int RS = NE * NF;  // 2560 row stride

    const float* Ab = lig_feat + (size_t)b * NL * RS + (size_t)e * NF;
    const float* Bb = rec_feat + (size_t)b * NR * RS + (size_t)e * NF + (size_t)n0 * RS;

#if HAS_TC
    const uint32_t sb = smem_u32(sm);
    if (tid == 0) {
        MBAR_INIT(sb + SM_FULL0, 256);
        MBAR_INIT(sb + SM_FULL1, 256);
        MBAR_INIT(sb + SM_EMPTY0, 1);
        MBAR_INIT(sb + SM_EMPTY1, 1);
        MBAR_INIT(sb + SM_DONE, 1);
    }
    if (wid == 0) {
        TC_ALLOC(sb + SM_TMEMP, 256);
        TC_RELINQ();
    }
    __syncthreads();
    uint32_t tmem;
    asm volatile("ld.shared.b32 %0, [%1];" : "=r"(tmem) : "r"(sb + SM_TMEMP));

    for (int chunk = 0; chunk < NCHUNK; chunk++) {
        const int s = chunk & 1;
        const int u = chunk >> 1;
        const int kb = chunk * BK;
        MBAR_WAIT(sb + (s ? SM_EMPTY1 : SM_EMPTY0), (u & 1) ^ 1);

        // A: 128 x 64 fp32 -> hi/lo bf16
#pragma unroll
        for (int i = 0; i < 8; i++) {
            int idx = tid + (i << 8);
            int row = idx >> 4;
            int col = (idx & 15) << 2;
            float4 v = *(const float4*)(Ab + (size_t)row * RS + kb + col);
            __nv_bfloat162 h01 = __floats2bfloat162_rn(v.x, v.y);
            __nv_bfloat162 h23 = __floats2bfloat162_rn(v.z, v.w);
            float2 f01 = __bfloat1622float2(h01);
            float2 f23 = __bfloat1622float2(h23);
            __nv_bfloat162 l01 = __floats2bfloat162_rn(v.x - f01.x, v.y - f01.y);
            __nv_bfloat162 l23 = __floats2bfloat162_rn(v.z - f23.x, v.w - f23.y);
            uint32_t so = swz(row * 128 + (col << 1));
            *(uint2*)(sm + AHI_OFF(s) + so) = make_uint2(pack2(h01), pack2(h23));
            *(uint2*)(sm + ALO_OFF(s) + so) = make_uint2(pack2(l01), pack2(l23));
        }
        // B: 256 x 64 fp32
#pragma unroll
        for (int i = 0; i < 16; i++) {
            int idx = tid + (i << 8);
            int row = idx >> 4;
            int col = (idx & 15) << 2;
            float4 v = *(const float4*)(Bb + (size_t)row * RS + kb + col);
            __nv_bfloat162 h01 = __floats2bfloat162_rn(v.x, v.y);
            __nv_bfloat162 h23 = __floats2bfloat162_rn(v.z, v.w);
            float2 f01 = __bfloat1622float2(h01);
            float2 f23 = __bfloat1622float2(h23);
            __nv_bfloat162 l01 = __floats2bfloat162_rn(v.x - f01.x, v.y - f01.y);
            __nv_bfloat162 l23 = __floats2bfloat162_rn(v.z - f23.x, v.w - f23.y);
            uint32_t so = swz(row * 128 + (col << 1));
            *(uint2*)(sm + BHI_OFF(s) + so) = make_uint2(pack2(h01), pack2(h23));
            *(uint2*)(sm + BLO_OFF(s) + so) = make_uint2(pack2(l01), pack2(l23));
        }
        FENCE_ASYNC_SHARED();
        MBAR_ARRIVE(sb + (s ? SM_FULL1 : SM_FULL0));

        if (tid == 0) {
            MBAR_WAIT(sb + (s ? SM_FULL1 : SM_FULL0), u & 1);
            uint64_t ah = make_desc(sb + AHI_OFF(s));
            uint64_t al = make_desc(sb + ALO_OFF(s));
            uint64_t bh = make_desc(sb + BHI_OFF(s));
            uint64_t bl = make_desc(sb + BLO_OFF(s));
#pragma unroll
            for (int ks = 0; ks < 4; ks++) {
                uint64_t o = ks * 2;
                mma_bf16_ss(tmem, ah + o, bh + o, IDESC, !(chunk == 0 && ks == 0));
                mma_bf16_ss(tmem, ah + o, bl + o, IDESC, 1u);
                mma_bf16_ss(tmem, al + o, bh + o, IDESC, 1u);
            }
            TC_COMMIT(sb + (s ? SM_EMPTY1 : SM_EMPTY0));
        }
    }
    if (tid == 0) TC_COMMIT(sb + SM_DONE);
    MBAR_WAIT(sb + SM_DONE, 0);
    TC_FENCE_AFTER();

    // epilogue: warp w -> rows (w&3)*32+lane, cols (w>>2)*128 .. +127
    const int lc = __ldg(&ligc[b]);
    const int rc = __ldg(&recc[b]);
    const int lane = tid & 31;
    const int l = (wid & 3) * 32 + lane;
    const int colb = (wid >> 2) * 128;
    const bool lok = l < lc;
    float* Crow = g_atn + ((size_t)(b * NE + e) * NL + l) * NR + n0 + colb;
#pragma unroll
    for (int cc = 0; cc < 4; cc++) {
        uint32_t r32[32];
        TC_LD_X32(r32, tmem + colb + cc * 32);
        TC_WAIT_LD();
        int rbase = n0 + colb + cc * 32;
#pragma unroll
        for (int j = 0; j < 32; j += 4) {
            float4 o;
            o.x = (lok && (rbase + j + 0) < rc) ? __uint_as_float(r32[j + 0]) : 0.f;
            o.y = (lok && (rbase + j + 1) < rc) ? __uint_as_float(r32[j + 1]) : 0.f;
            o.z = (lok && (rbase + j + 2) < rc) ? __uint_as_float(r32[j + 2]) : 0.f;
            o.w = (lok && (rbase + j + 3) < rc) ? __uint_as_float(r32[j + 3]) : 0.f;
            *(float4*)(Crow + cc * 32 + j) = o;
        }
    }
    TC_FENCE_BEFORE();
    __syncthreads();
    if (wid == 0) TC_DEALLOC(tmem, 256);

#else  // ------------------------- SIMT fp32 fallback --------------------------
    (void)wid;
    float* As = (float*)sm;            // [16][132]
    float* Bs = As + 16 * 132;         // [16][132]
    const int lc = __ldg(&ligc[b]);
    const int rc = __ldg(&recc[b]);
    const int rt = tid >> 4;           // 0..15
    const int ct = tid & 15;           // 0..15
    const int lrow = tid >> 1;         // 0..127
    const int lcol = (tid & 1) << 3;   // 0 or 8

    for (int h = 0; h < 2; h++) {
        float acc[8][8];
#pragma unroll
        for (int i = 0; i < 8; i++)
#pragma unroll
            for (int j = 0; j < 8; j++) acc[i][j] = 0.f;
        const float* Bh = Bb + (size_t)(h * 128) * RS;

        for (int k0 = 0; k0 < NF; k0 += 16) {
            float4 a0 = *(const float4*)(Ab + (size_t)lrow * RS + k0 + lcol);
            float4 a1 = *(const float4*)(Ab + (size_t)lrow * RS + k0 + lcol + 4);
            float4 b0 = *(const float4*)(Bh + (size_t)lrow * RS + k0 + lcol);
            float4 b1 = *(const float4*)(Bh + (size_t)lrow * RS + k0 + lcol + 4);
            __syncthreads();
            As[(lcol + 0) * 132 + lrow] = a0.x;
            As[(lcol + 1) * 132 + lrow] = a0.y;
            As[(lcol + 2) * 132 + lrow] = a0.z;
            As[(lcol + 3) * 132 + lrow] = a0.w;
            As[(lcol + 4) * 132 + lrow] = a1.x;
            As[(lcol + 5) * 132 + lrow] = a1.y;
            As[(lcol + 6) * 132 + lrow] = a1.z;
            As[(lcol + 7) * 132 + lrow] = a1.w;
            Bs[(lcol + 0) * 132 + lrow] = b0.x;
            Bs[(lcol + 1) * 132 + lrow] = b0.y;
            Bs[(lcol + 2) * 132 + lrow] = b0.z;
            Bs[(lcol + 3) * 132 + lrow] = b0.w;
            Bs[(lcol + 4) * 132 + lrow] = b1.x;
            Bs[(lcol + 5) * 132 + lrow] = b1.y;
            Bs[(lcol + 6) * 132 + lrow] = b1.z;
            Bs[(lcol + 7) * 132 + lrow] = b1.w;
            __syncthreads();
#pragma unroll
            for (int k = 0; k < 16; k++) {
                float4 av0 = *(float4*)&As[k * 132 + rt * 8];
                float4 av1 = *(float4*)&As[k * 132 + rt * 8 + 4];
                float4 bv0 = *(float4*)&Bs[k * 132 + ct * 8];
                float4 bv1 = *(float4*)&Bs[k * 132 + ct * 8 + 4];
                float ar[8] = {av0.x, av0.y, av0.z, av0.w, av1.x, av1.y, av1.z, av1.w};
                float br[8] = {bv0.x, bv0.y, bv0.z, bv0.w, bv1.x, bv1.y, bv1.z, bv1.w};
#pragma unroll
                for (int i = 0; i < 8; i++)
#pragma unroll
                    for (int j = 0; j < 8; j++)
                        acc[i][j] = fmaf(ar[i], br[j], acc[i][j]);
            }
        }
        // masked store
#pragma unroll
        for (int i = 0; i < 8; i++) {
            int l = rt * 8 + i;
            bool lok = l < lc;
            int c0 = n0 + h * 128 + ct * 8;
            float* Crow = g_atn + ((size_t)(b * NE + e) * NL + l) * NR;
            float4 o1, o2;
            o1.x = (lok && (c0 + 0) < rc) ? acc[i][0] : 0.f;
            o1.y = (lok && (c0 + 1) < rc) ? acc[i][1] : 0.f;
            o1.z = (lok && (c0 + 2) < rc) ? acc[i][2] : 0.f;
            o1.w = (lok && (c0 + 3) < rc) ? acc[i][3] : 0.f;
            o2.x = (lok && (c0 + 4) < rc) ? acc[i][4] : 0.f;
            o2.y = (lok && (c0 + 5) < rc) ? acc[i][5] : 0.f;
            o2.z = (lok && (c0 + 6) < rc) ? acc[i][6] : 0.f;
            o2.w = (lok && (c0 + 7) < rc) ? acc[i][7] : 0.f;
            *(float4*)(Crow + c0) = o1;
            *(float4*)(Crow + c0 + 4) = o2;
        }
        __syncthreads();
    }
#endif
}

// ---------------------------------------------------------------------------
// Kernel 3: U[b,t] = sum_{l,r,e} atn * dist^exp, exps = [-3,-2,-1,1,2]
// ---------------------------------------------------------------------------
__global__ void __launch_bounds__(256) energy_kernel(const float* __restrict__ rec_coord,
                                                     float* __restrict__ out) {
    const int b = blockIdx.y;
    const int l0 = blockIdx.x * 2;
    const int tid = threadIdx.x;

    __shared__ float s_lig[2][NT][3];
    if (tid < 96) {
        int li = tid / 48, rem = tid % 48, t = rem / 3, c = rem % 3;
        s_lig[li][t][c] = g_newlig[((b * NT + t) * NL + (l0 + li)) * 3 + c];
    }
    __syncthreads();

    float acc[NT];
#pragma unroll
    for (int t = 0; t < NT; t++) acc[t] = 0.f;

    const float* rcb = rec_coord + (size_t)b * NR * 3;
    const size_t estride = (size_t)NL * NR;

#pragma unroll
    for (int li = 0; li < 2; li++) {
        const int l = l0 + li;
        const float* atn0 = g_atn + ((size_t)b * NE * NL + l) * NR;
        for (int r = tid; r < NR; r += 256) {
            float a0 = atn0[r];
            float a1 = atn0[estride + r];
            float a2 = atn0[2 * estride + r];
            float a3 = atn0[3 * estride + r];
            float a4 = atn0[4 * estride + r];
            float cx = rcb[r * 3 + 0], cy = rcb[r * 3 + 1], cz = rcb[r * 3 + 2];
#pragma unroll
            for (int t = 0; t < NT; t++) {
                float dx = s_lig[li][t][0] - cx;
                float dy = s_lig[li][t][1] - cy;
                float dz = s_lig[li][t][2] - cz;
                float d2 = fmaf(dx, dx, fmaf(dy, dy, dz * dz));
                d2 = fmaxf(d2, 1e-12f);
                float inv = rsqrtf(d2);
                float inv2 = inv * inv;
                float inv3 = inv2 * inv;
                float d = d2 * inv;
                acc[t] += fmaf(a0, inv3, fmaf(a1, inv2, fmaf(a2, inv, fmaf(a3, d, a4 * d2))));
            }
        }
    }
#pragma unroll
    for (int t = 0; t < NT; t++) {
#pragma unroll
        for (int off = 16; off > 0; off >>= 1)
            acc[t] += __shfl_xor_sync(0xffffffffu, acc[t], off);
    }
    __shared__ float red[8][NT];
    int warp = tid >> 5, lane = tid & 31;
    if (lane == 0) {
#pragma unroll
        for (int t = 0; t < NT; t++) red[warp][t] = acc[t];
    }
    __syncthreads();
    if (tid < NT) {
        float s = 0.f;
#pragma unroll
        for (int w = 0; w < 8; w++) s += red[w][tid];
        atomicAdd(&out[b * NT + tid], s);
    }
}

// ---------------------------------------------------------------------------
extern "C" void kernel_launch(void* const* d_in, const int* in_sizes, int n_in,
                              void* d_out, int out_size) {
    (void)in_sizes; (void)n_in; (void)out_size;
    const float* lig_feat   = (const float*)d_in[0];
    const float* rec_feat   = (const float*)d_in[1];
    const float* lig_coord  = (const float*)d_in[2];
    const float* rec_coord  = (const float*)d_in[3];
    const float* pre_rot    = (const float*)d_in[4];
    const float* trans      = (const float*)d_in[5];
    const int*   lig_counts = (const int*)d_in[6];
    const int*   rec_counts = (const int*)d_in[7];
    float* out = (float*)d_out;

    cudaFuncSetAttribute(atn_gemm_tc, cudaFuncAttributeMaxDynamicSharedMemorySize, GEMM_SMEM);

    rot_kernel<<<NB * NT, NL>>>(pre_rot, lig_coord, trans, out);

    dim3 g1(NR / BN, NB * NE);
    atn_gemm_tc<<<g1, 256, GEMM_SMEM>>>(lig_feat, rec_feat, lig_counts, rec_counts);

    dim3 g2(NL / 2, NB);
    energy_kernel<<<g2, 256>>>(rec_coord, out);
}

// round 4
// speedup vs baseline: 2.4731x; 1.1202x over previous
#include <cuda_runtime.h>
#include <cuda_bf16.h>
#include <math.h>
#include <stdint.h>

#define NB 8
#define NT 16
#define NL 128
#define NR 1024
#define NE 5
#define NF 512

#define BRN 64            // r-tile per CTA (MMA N)
#define BKF 64            // fp32 K per chunk
#define NITER (NE * (NF / BKF))   // 40

// tcgen05 / f32x2 are "a"-features: only emit in arch-specific passes.
#if defined(__CUDA_ARCH__) && (defined(__CUDA_ARCH_FEAT_SM103_ALL) || defined(__CUDA_ARCH_FEAT_SM100_ALL))
#define HAS_TC 1
#else
#define HAS_TC 0
#endif

__device__ float g_part[NB * 16 * NT];   // [b][rtile][t]

// ---------------------------------------------------------------- helpers
__device__ __forceinline__ uint32_t smem_u32(const void* p) {
    uint32_t a;
    asm("{ .reg .u64 t; cvta.to.shared.u64 t, %1; cvt.u32.u64 %0, t; }" : "=r"(a) : "l"(p));
    return a;
}

#if HAS_TC
#define MBAR_INIT(a, n) asm volatile("mbarrier.init.shared.b64 [%0], %1;" :: "r"(a), "r"(n) : "memory")
#define MBAR_ARRIVE(a)  asm volatile("mbarrier.arrive.shared.b64 _, [%0];" :: "r"(a) : "memory")
#define MBAR_WAIT(a, ph) do {                                                     \
    uint32_t _m = (a), _p = (ph), _d;                                             \
    asm volatile("{\n\t.reg .pred p;\n\t"                                         \
        "mbarrier.try_wait.parity.acquire.cta.shared::cta.b64 p, [%1], %2;\n\t"   \
        "selp.b32 %0, 1, 0, p;\n\t}" : "=r"(_d) : "r"(_m), "r"(_p) : "memory");   \
    if (!_d) {                                                                    \
        asm volatile("{\n\t.reg .pred P1;\n\tW%=:\n\t"                            \
            "mbarrier.try_wait.parity.acquire.cta.shared::cta.b64 P1, [%0], %1, 0x989680;\n\t" \
            "@P1 bra.uni D%=;\n\tbra.uni W%=;\n\tD%=:\n\t}"                       \
            :: "r"(_m), "r"(_p) : "memory");                                      \
    }                                                                             \
} while (0)
#define FENCE_ASYNC_SHARED() asm volatile("fence.proxy.async.shared::cta;" ::: "memory")
#define TC_ALLOC(sm_, n)  asm volatile("tcgen05.alloc.cta_group::1.sync.aligned.shared::cta.b32 [%0], %1;" :: "r"(sm_), "r"(n) : "memory")
#define TC_DEALLOC(t, n)  asm volatile("tcgen05.dealloc.cta_group::1.sync.aligned.b32 %0, %1;" :: "r"(t), "r"(n))
#define TC_RELINQ()       asm volatile("tcgen05.relinquish_alloc_permit.cta_group::1.sync.aligned;")
#define TC_COMMIT(mb)     asm volatile("tcgen05.commit.cta_group::1.mbarrier::arrive::one.shared::cluster.b64 [%0];" :: "r"(mb) : "memory")
#define TC_FENCE_AFTER()  asm volatile("tcgen05.fence::after_thread_sync;" ::: "memory")
#define TC_FENCE_BEFORE() asm volatile("tcgen05.fence::before_thread_sync;" ::: "memory")
#define TC_WAIT_LD()      asm volatile("tcgen05.wait::ld.sync.aligned;" ::: "memory")

#define TC_LD_X16(r, ta) \
    asm volatile("tcgen05.ld.sync.aligned.32x32b.x16.b32 " \
        "{%0,%1,%2,%3,%4,%5,%6,%7,%8,%9,%10,%11,%12,%13,%14,%15}, [%16];" \
        : "=r"((r)[0]),"=r"((r)[1]),"=r"((r)[2]),"=r"((r)[3]), \
          "=r"((r)[4]),"=r"((r)[5]),"=r"((r)[6]),"=r"((r)[7]), \
          "=r"((r)[8]),"=r"((r)[9]),"=r"((r)[10]),"=r"((r)[11]), \
          "=r"((r)[12]),"=r"((r)[13]),"=r"((r)[14]),"=r"((r)[15]) \
        : "r"(ta))

// SW128 K-major SMEM descriptor
__device__ __forceinline__ uint64_t make_desc(uint32_t addr) {
    const uint64_t base =
        (uint64_t(2) << 61) | (uint64_t(1) << 46) | (uint64_t(64) << 32) | (uint64_t(1) << 16);
    return base | ((uint64_t)(addr >> 4) & 0x3FFF);
}
__device__ __forceinline__ void mma_bf16_ss(uint32_t d, uint64_t ad, uint64_t bd,
                                            uint32_t idesc, uint32_t en) {
    asm volatile("{\n\t.reg .pred p;\n\tsetp.ne.u32 p, %4, 0;\n\t"
        "tcgen05.mma.cta_group::1.kind::f16 [%0], %1, %2, %3, {%5,%5,%5,%5}, p;\n\t}"
        :: "r"(d), "l"(ad), "l"(bd), "r"(idesc), "r"(en), "r"(0u) : "memory");
}
// f32x2 packed math
#define FMA2(d, a, b, c) asm("fma.rn.f32x2 %0, %1, %2, %3;" : "=l"(d) : "l"(a), "l"(b), "l"(c))
#define ADD2(d, a, b)    asm("add.rn.f32x2 %0, %1, %2;"     : "=l"(d) : "l"(a), "l"(b))
#define MUL2(d, a, b)    asm("mul.rn.f32x2 %0, %1, %2;"     : "=l"(d) : "l"(a), "l"(b))
#define PACK2(d, lo, hi)  asm("mov.b64 %0, {%1, %2};" : "=l"(d) : "r"(lo), "r"(hi))
#define UNPACK2(lo, hi, s) asm("mov.b64 {%0, %1}, %2;" : "=r"(lo), "=r"(hi) : "l"(s))
#endif  // HAS_TC

// idesc: F32 accum, BF16 a/b, N=64, M=128
#define IDESC ((1u << 4) | (1u << 7) | (1u << 10) | ((BRN / 8) << 17) | ((128 / 16) << 24))

// SMEM layout
#define SM_TMEMP 0
#define SM_FULL0 16
#define SM_FULL1 24
#define SM_EMPTY0 32
#define SM_EMPTY1 40
#define SM_DONE 48
#define SROT_OFF 64            // 16*12 floats = 768B
#define SQ_OFF 832             // 3*64 floats (negated rec coords) = 768B
#define RED_OFF 1600           // 8*16 floats = 512B
#define STAGE0 3072
#define STAGE_BYTES 49152      // AHI 16K + ALO 16K + BHI 8K + BLO 8K
#define AHI_OFF(s) (STAGE0 + (s) * STAGE_BYTES)
#define ALO_OFF(s) (AHI_OFF(s) + 16384)
#define BHI_OFF(s) (AHI_OFF(s) + 32768)
#define BLO_OFF(s) (AHI_OFF(s) + 40960)
#define FUSED_SMEM (STAGE0 + 2 * STAGE_BYTES)   // 101376

__device__ __forceinline__ uint32_t swz(uint32_t off) { return off ^ ((off >> 3) & 0x70); }
__device__ __forceinline__ uint32_t packbf2(__nv_bfloat162 v) {
    return *reinterpret_cast<uint32_t*>(&v);
}

// ---------------------------------------------------------------------------
// Fused kernel: QR + GEMM (tcgen05, bf16 hi/lo split) + energy epilogue.
// grid = (16 rtiles, 8 b), 256 threads.
// ---------------------------------------------------------------------------
__global__ void __launch_bounds__(256, 1) fused_energy(
    const float* __restrict__ lig_feat,
    const float* __restrict__ rec_feat,
    const float* __restrict__ lig_coord,
    const float* __restrict__ rec_coord,
    const float* __restrict__ pre_rot,
    const float* __restrict__ trans,
    const int* __restrict__ ligc,
    const int* __restrict__ recc) {
    extern __shared__ char sm[];
    const int tid = threadIdx.x;
    const int b = blockIdx.y;
    const int rtile = blockIdx.x;
    const int r0 = rtile * BRN;
    const int RS = NE * NF;                // 2560

    float* s_rot = (float*)(sm + SROT_OFF);   // [16][12]: Q row-major + trans
    float* s_qx = (float*)(sm + SQ_OFF);      // negated rec coords, 64 each
    float* s_qy = s_qx + 64;
    float* s_qz = s_qx + 128;
    float* s_red = (float*)(sm + RED_OFF);    // [8][16]

    // ---- Phase 0: QR (LAPACK convention) for 16 timesteps + neg rec coords
    if (tid < NT) {
        const int t = tid;
        const float* A0 = pre_rot + (b * NT + t) * 9;
        float a00 = A0[0], a01 = A0[1], a02 = A0[2];
        float a10 = A0[3], a11 = A0[4], a12 = A0[5];
        float a20 = A0[6], a21 = A0[7], a22 = A0[8];
        float v1 = 0.f, v2 = 0.f, tau0 = 0.f;
        float xn2 = a10 * a10 + a20 * a20;
        if (xn2 > 0.f) {
            float beta = -copysignf(sqrtf(a00 * a00 + xn2), a00);
            tau0 = (beta - a00) / beta;
            float inv = 1.f / (a00 - beta);
            v1 = a10 * inv; v2 = a20 * inv;
            float w1 = a01 + v1 * a11 + v2 * a21;
            a01 -= tau0 * w1; a11 -= tau0 * v1 * w1; a21 -= tau0 * v2 * w1;
            float w2 = a02 + v1 * a12 + v2 * a22;
            a02 -= tau0 * w2; a12 -= tau0 * v1 * w2; a22 -= tau0 * v2 * w2;
        }
        float u2 = 0.f, tau1 = 0.f;
        if (a21 != 0.f) {
            float beta1 = -copysignf(sqrtf(a11 * a11 + a21 * a21), a11);
            tau1 = (beta1 - a11) / beta1;
            u2 = a21 / (a11 - beta1);
        }
        float H0m[3][3] = {
            {1.f - tau0, -tau0 * v1, -tau0 * v2},
            {-tau0 * v1, 1.f - tau0 * v1 * v1, -tau0 * v1 * v2},
            {-tau0 * v2, -tau0 * v1 * v2, 1.f - tau0 * v2 * v2}};
        float H1m[3][3] = {
            {1.f, 0.f, 0.f},
            {0.f, 1.f - tau1, -tau1 * u2},
            {0.f, -tau1 * u2, 1.f - tau1 * u2 * u2}};
#pragma unroll
        for (int i = 0; i < 3; i++)
#pragma unroll
            for (int jj = 0; jj < 3; jj++)
                s_rot[t * 12 + i * 3 + jj] =
                    H0m[i][0] * H1m[0][jj] + H0m[i][1] * H1m[1][jj] + H0m[i][2] * H1m[2][jj];
        s_rot[t * 12 + 9]  = trans[(b * NT + t) * 3 + 0];
        s_rot[t * 12 + 10] = trans[(b * NT + t) * 3 + 1];
        s_rot[t * 12 + 11] = trans[(b * NT + t) * 3 + 2];
    }
    if (tid >= 64 && tid < 128) {
        int r = r0 + (tid - 64);
        s_qx[tid - 64] = -rec_coord[((size_t)b * NR + r) * 3 + 0];
        s_qy[tid - 64] = -rec_coord[((size_t)b * NR + r) * 3 + 1];
        s_qz[tid - 64] = -rec_coord[((size_t)b * NR + r) * 3 + 2];
    }

    const int lc = __ldg(&ligc[b]);
    const int rc = __ldg(&recc[b]);
    const int lane = tid & 31;
    const int w = tid >> 5;

#if HAS_TC
    const uint32_t sb = smem_u32(sm);
    if (tid == 0) {
        MBAR_INIT(sb + SM_FULL0, 256);
        MBAR_INIT(sb + SM_FULL1, 256);
        MBAR_INIT(sb + SM_EMPTY0, 1);
        MBAR_INIT(sb + SM_EMPTY1, 1);
        MBAR_INIT(sb + SM_DONE, 1);
    }
    if (w == 0) {
        TC_ALLOC(sb + SM_TMEMP, 512);
        TC_RELINQ();
    }
    __syncthreads();
    uint32_t tmem;
    asm volatile("ld.shared.b32 %0, [%1];" : "=r"(tmem) : "r"(sb + SM_TMEMP));

    const float* Abase = lig_feat + (size_t)b * NL * RS;
    const float* Bbase = rec_feat + ((size_t)b * NR + r0) * RS;

    // ---- Phase 1: pipelined load/convert + MMA over 40 (e, kchunk) iters
    for (int iter = 0; iter < NITER; iter++) {
        const int e = iter >> 3;
        const int kc = iter & 7;
        const int s = iter & 1;
        const int u = iter >> 1;
        const float* Ae = Abase + e * NF + kc * BKF;
        const float* Be = Bbase + e * NF + kc * BKF;

        MBAR_WAIT(sb + (s ? SM_EMPTY1 : SM_EMPTY0), (u & 1) ^ 1);

        // A: 128 x 64 fp32 -> hi/lo bf16
#pragma unroll
        for (int i = 0; i < 8; i++) {
            int idx = tid + (i << 8);
            int row = idx >> 4;
            int col = (idx & 15) << 2;
            float4 v = *(const float4*)(Ae + (size_t)row * RS + col);
            __nv_bfloat162 h01 = __floats2bfloat162_rn(v.x, v.y);
            __nv_bfloat162 h23 = __floats2bfloat162_rn(v.z, v.w);
            float2 f01 = __bfloat1622float2(h01);
            float2 f23 = __bfloat1622float2(h23);
            __nv_bfloat162 l01 = __floats2bfloat162_rn(v.x - f01.x, v.y - f01.y);
            __nv_bfloat162 l23 = __floats2bfloat162_rn(v.z - f23.x, v.w - f23.y);
            uint32_t so = swz(row * 128 + (col << 1));
            *(uint2*)(sm + AHI_OFF(s) + so) = make_uint2(packbf2(h01), packbf2(h23));
            *(uint2*)(sm + ALO_OFF(s) + so) = make_uint2(packbf2(l01), packbf2(l23));
        }
        // B: 64 x 64 fp32 -> hi/lo bf16
#pragma unroll
        for (int i = 0; i < 4; i++) {
            int idx = tid + (i << 8);
            int row = idx >> 4;
            int col = (idx & 15) << 2;
            float4 v = *(const float4*)(Be + (size_t)row * RS + col);
            __nv_bfloat162 h01 = __floats2bfloat162_rn(v.x, v.y);
            __nv_bfloat162 h23 = __floats2bfloat162_rn(v.z, v.w);
            float2 f01 = __bfloat1622float2(h01);
            float2 f23 = __bfloat1622float2(h23);
            __nv_bfloat162 l01 = __floats2bfloat162_rn(v.x - f01.x, v.y - f01.y);
            __nv_bfloat162 l23 = __floats2bfloat162_rn(v.z - f23.x, v.w - f23.y);
            uint32_t so = swz(row * 128 + (col << 1));
            *(uint2*)(sm + BHI_OFF(s) + so) = make_uint2(packbf2(h01), packbf2(h23));
            *(uint2*)(sm + BLO_OFF(s) + so) = make_uint2(packbf2(l01), packbf2(l23));
        }
        FENCE_ASYNC_SHARED();
        MBAR_ARRIVE(sb + (s ? SM_FULL1 : SM_FULL0));

        if (tid == 0) {
            MBAR_WAIT(sb + (s ? SM_FULL1 : SM_FULL0), u & 1);
            uint64_t ah = make_desc(sb + AHI_OFF(s));
            uint64_t al = make_desc(sb + ALO_OFF(s));
            uint64_t bh = make_desc(sb + BHI_OFF(s));
            uint64_t bl = make_desc(sb + BLO_OFF(s));
            uint32_t dcol = tmem + e * 64;
#pragma unroll
            for (int ks = 0; ks < 4; ks++) {
                uint64_t o = ks * 2;
                mma_bf16_ss(dcol, ah + o, bh + o, IDESC, !(kc == 0 && ks == 0));
                mma_bf16_ss(dcol, ah + o, bl + o, IDESC, 1u);
                mma_bf16_ss(dcol, al + o, bh + o, IDESC, 1u);
            }
            TC_COMMIT(sb + (s ? SM_EMPTY1 : SM_EMPTY0));
        }
    }
    if (tid == 0) TC_COMMIT(sb + SM_DONE);
    MBAR_WAIT(sb + SM_DONE, 0);
    TC_FENCE_AFTER();

    // ---- Phase 2: energy epilogue (f32x2 packed over r-pairs)
    // warp w: l-rows (w&3)*32+lane, r-cols (w>>2)*32 .. +31
    const int l = (w & 3) * 32 + lane;
    const int rhalf = w >> 2;
    const bool lok = l < lc;
    const float xl = lig_coord[((size_t)b * NL + l) * 3 + 0];
    const float yl = lig_coord[((size_t)b * NL + l) * 3 + 1];
    const float zl = lig_coord[((size_t)b * NL + l) * 3 + 2];

    uint64_t acc2[NT];
#pragma unroll
    for (int t = 0; t < NT; t++) acc2[t] = 0ull;
    uint64_t eps2;
    PACK2(eps2, __float_as_uint(1e-12f), __float_as_uint(1e-12f));

#pragma unroll
    for (int c = 0; c < 2; c++) {
        const int colbase = rhalf * 32 + c * 16;
        uint32_t ar[NE][16];
#pragma unroll
        for (int e = 0; e < NE; e++) {
            TC_LD_X16(ar[e], tmem + e * 64 + colbase);
        }
        TC_WAIT_LD();
        // mask + pack to f32x2 pairs
        uint64_t A2[NE][8];
        const int rgbase = r0 + colbase;
#pragma unroll
        for (int e = 0; e < NE; e++)
#pragma unroll
            for (int j = 0; j < 8; j++) {
                uint32_t v0 = (lok && (rgbase + 2 * j)     < rc) ? ar[e][2 * j]     : 0u;
                uint32_t v1 = (lok && (rgbase + 2 * j + 1) < rc) ? ar[e][2 * j + 1] : 0u;
                PACK2(A2[e][j], v0, v1);
            }
        const uint64_t* nqx = (const uint64_t*)(s_qx + colbase);
        const uint64_t* nqy = (const uint64_t*)(s_qy + colbase);
        const uint64_t* nqz = (const uint64_t*)(s_qz + colbase);
#pragma unroll
        for (int t = 0; t < NT; t++) {
            const float* Rt = s_rot + t * 12;
            float px = fmaf(Rt[0], xl, fmaf(Rt[1], yl, fmaf(Rt[2], zl, Rt[9])));
            float py = fmaf(Rt[3], xl, fmaf(Rt[4], yl, fmaf(Rt[5], zl, Rt[10])));
            float pz = fmaf(Rt[6], xl, fmaf(Rt[7], yl, fmaf(Rt[8], zl, Rt[11])));
            uint64_t px2, py2, pz2;
            PACK2(px2, __float_as_uint(px), __float_as_uint(px));
            PACK2(py2, __float_as_uint(py), __float_as_uint(py));
            PACK2(pz2, __float_as_uint(pz), __float_as_uint(pz));
            uint64_t a = acc2[t];
#pragma unroll
            for (int j = 0; j < 8; j++) {
                uint64_t dx, dy, dz, d2, t1, t2;
                ADD2(dx, px2, nqx[j]);
                ADD2(dy, py2, nqy[j]);
                ADD2(dz, pz2, nqz[j]);
                FMA2(t1, dz, dz, eps2);
                FMA2(t2, dy, dy, t1);
                FMA2(d2, dx, dx, t2);
                uint32_t lo, hi;
                UNPACK2(lo, hi, d2);
                float ia = rsqrtf(__uint_as_float(lo));
                float ib = rsqrtf(__uint_as_float(hi));
                uint64_t inv, inv2, inv3, dd;
                PACK2(inv, __float_as_uint(ia), __float_as_uint(ib));
                MUL2(inv2, inv, inv);
                MUL2(inv3, inv2, inv);
                MUL2(dd, d2, inv);
                FMA2(a, A2[0][j], inv3, a);
                FMA2(a, A2[1][j], inv2, a);
                FMA2(a, A2[2][j], inv, a);
                FMA2(a, A2[3][j], dd, a);
                FMA2(a, A2[4][j], d2, a);
            }
            acc2[t] = a;
        }
    }
    TC_FENCE_BEFORE();
    __syncthreads();
    if (w == 0) TC_DEALLOC(tmem, 512);

    float accf[NT];
#pragma unroll
    for (int t = 0; t < NT; t++) {
        uint32_t lo, hi;
        UNPACK2(lo, hi, acc2[t]);
        accf[t] = __uint_as_float(lo) + __uint_as_float(hi);
    }

#else  // ------------------------- SIMT fallback (non-'a' pass) -------------
    __syncthreads();
    // group of 4 threads per r
    const int g = tid >> 2;
    const int j4 = tid & 3;
    const int r = r0 + g;
    const bool rok = r < rc;
    const float qx = rec_coord[((size_t)b * NR + r) * 3 + 0];
    const float qy = rec_coord[((size_t)b * NR + r) * 3 + 1];
    const float qz = rec_coord[((size_t)b * NR + r) * 3 + 2];
    float accf[NT];
#pragma unroll
    for (int t = 0; t < NT; t++) accf[t] = 0.f;

    for (int l = 0; l < NL; l++) {
        float dot[NE];
#pragma unroll
        for (int e = 0; e < NE; e++) dot[e] = 0.f;
        if (l < lc && rok) {
            const float* Arow = lig_feat + ((size_t)b * NL + l) * RS;
            const float* Brow = rec_feat + ((size_t)b * NR + r) * RS;
#pragma unroll
            for (int e = 0; e < NE; e++) {
                float sacc = 0.f;
                for (int f = j4 * 4; f < NF; f += 16) {
                    float4 av = *(const float4*)(Arow + e * NF + f);
                    float4 bv = *(const float4*)(Brow + e * NF + f);
                    sacc += av.x * bv.x + av.y * bv.y + av.z * bv.z + av.w * bv.w;
                }
                dot[e] = sacc;
            }
        }
#pragma unroll
        for (int e = 0; e < NE; e++) {
            dot[e] += __shfl_xor_sync(0xffffffffu, dot[e], 1);
            dot[e] += __shfl_xor_sync(0xffffffffu, dot[e], 2);
        }
        float xl = lig_coord[((size_t)b * NL + l) * 3 + 0];
        float yl = lig_coord[((size_t)b * NL + l) * 3 + 1];
        float zl = lig_coord[((size_t)b * NL + l) * 3 + 2];
        for (int t = j4; t < NT; t += 4) {
            const float* Rt = s_rot + t * 12;
            float px = fmaf(Rt[0], xl, fmaf(Rt[1], yl, fmaf(Rt[2], zl, Rt[9])));
            float py = fmaf(Rt[3], xl, fmaf(Rt[4], yl, fmaf(Rt[5], zl, Rt[10])));
            float pz = fmaf(Rt[6], xl, fmaf(Rt[7], yl, fmaf(Rt[8], zl, Rt[11])));
            float dx = px - qx, dy = py - qy, dz = pz - qz;
            float d2 = fmaf(dx, dx, fmaf(dy, dy, dz * dz));
            d2 = fmaxf(d2, 1e-12f);
            float inv = rsqrtf(d2);
            float inv2 = inv * inv;
            float inv3 = inv2 * inv;
            float d = d2 * inv;
            accf[t] += fmaf(dot[0], inv3, fmaf(dot[1], inv2,
                          fmaf(dot[2], inv, fmaf(dot[3], d, dot[4] * d2))));
        }
    }
#endif

    // ---- common block reduction -> g_part[b][rtile][t]
#pragma unroll
    for (int t = 0; t < NT; t++) {
#pragma unroll
        for (int off = 16; off > 0; off >>= 1)
            accf[t] += __shfl_xor_sync(0xffffffffu, accf[t], off);
    }
    if (lane == 0) {
#pragma unroll
        for (int t = 0; t < NT; t++) s_red[w * NT + t] = accf[t];
    }
    __syncthreads();
    if (tid < NT) {
        float s = 0.f;
#pragma unroll
        for (int ww = 0; ww < 8; ww++) s += s_red[ww * NT + tid];
        g_part[(b * 16 + rtile) * NT + tid] = s;
    }
}

// ---------------------------------------------------------------------------
__global__ void finish_kernel(float* __restrict__ out) {
    int tid = threadIdx.x;   // 128
    int b = tid >> 4, t = tid & 15;
    float s = 0.f;
#pragma unroll
    for (int rt = 0; rt < 16; rt++) s += g_part[(b * 16 + rt) * NT + t];
    out[b * NT + t] = s;
}

// ---------------------------------------------------------------------------
extern "C" void kernel_launch(void* const* d_in, const int* in_sizes, int n_in,
                              void* d_out, int out_size) {
    (void)in_sizes; (void)n_in; (void)out_size;
    const float* lig_feat   = (const float*)d_in[0];
    const float* rec_feat   = (const float*)d_in[1];
    const float* lig_coord  = (const float*)d_in[2];
    const float* rec_coord  = (const float*)d_in[3];
    const float* pre_rot    = (const float*)d_in[4];
    const float* trans      = (const float*)d_in[5];
    const int*   lig_counts = (const int*)d_in[6];
    const int*   rec_counts = (const int*)d_in[7];
    float* out = (float*)d_out;

    cudaFuncSetAttribute(fused_energy, cudaFuncAttributeMaxDynamicSharedMemorySize, FUSED_SMEM);

    dim3 g1(16, NB);
    fused_energy<<<g1, 256, FUSED_SMEM>>>(lig_feat, rec_feat, lig_coord, rec_coord,
                                          pre_rot, trans, lig_counts, rec_counts);
    finish_kernel<<<1, 128>>>(out);
}

// round 7
// speedup vs baseline: 2.6895x; 1.0875x over previous
#include <cuda_runtime.h>
#include <cuda_bf16.h>
#include <math.h>
#include <stdint.h>

#define NB 8
#define NT 16
#define NL 128
#define NR 1024
#define NE 5
#define NF 512

#define BRN 64            // r-tile per CTA (MMA N)
#define BKF 64            // fp32 K per chunk
#define NITER (NE * (NF / BKF))   // 40
#define NSTAGE 3

// tcgen05 / f32x2 are "a"-features: only emit in arch-specific passes.
#if defined(__CUDA_ARCH__) && (defined(__CUDA_ARCH_FEAT_SM103_ALL) || defined(__CUDA_ARCH_FEAT_SM100_ALL))
#define HAS_TC 1
#else
#define HAS_TC 0
#endif

__device__ float g_part[NB * 16 * NT];   // [b][rtile][t]
__device__ unsigned int g_ctr;           // monotonically increasing CTA-done counter

// ---------------------------------------------------------------- helpers
__device__ __forceinline__ uint32_t smem_u32(const void* p) {
    uint32_t a;
    asm("{ .reg .u64 t; cvta.to.shared.u64 t, %1; cvt.u32.u64 %0, t; }" : "=r"(a) : "l"(p));
    return a;
}

#if HAS_TC
#define MBAR_INIT(a, n) asm volatile("mbarrier.init.shared.b64 [%0], %1;" :: "r"(a), "r"(n) : "memory")
#define MBAR_ARRIVE(a)  asm volatile("mbarrier.arrive.shared.b64 _, [%0];" :: "r"(a) : "memory")
#define MBAR_WAIT(a, ph) do {                                                     \
    uint32_t _m = (a), _p = (ph), _d;                                             \
    asm volatile("{\n\t.reg .pred p;\n\t"                                         \
        "mbarrier.try_wait.parity.acquire.cta.shared::cta.b64 p, [%1], %2;\n\t"   \
        "selp.b32 %0, 1, 0, p;\n\t}" : "=r"(_d) : "r"(_m), "r"(_p) : "memory");   \
    if (!_d) {                                                                    \
        asm volatile("{\n\t.reg .pred P1;\n\tW%=:\n\t"                            \
            "mbarrier.try_wait.parity.acquire.cta.shared::cta.b64 P1, [%0], %1, 0x989680;\n\t" \
            "@P1 bra.uni D%=;\n\tbra.uni W%=;\n\tD%=:\n\t}"                       \
            :: "r"(_m), "r"(_p) : "memory");                                      \
    }                                                                             \
} while (0)
#define FENCE_ASYNC_SHARED() asm volatile("fence.proxy.async.shared::cta;" ::: "memory")
#define TC_ALLOC(sm_, n)  asm volatile("tcgen05.alloc.cta_group::1.sync.aligned.shared::cta.b32 [%0], %1;" :: "r"(sm_), "r"(n) : "memory")
#define TC_DEALLOC(t, n)  asm volatile("tcgen05.dealloc.cta_group::1.sync.aligned.b32 %0, %1;" :: "r"(t), "r"(n))
#define TC_RELINQ()       asm volatile("tcgen05.relinquish_alloc_permit.cta_group::1.sync.aligned;")
#define TC_COMMIT(mb)     asm volatile("tcgen05.commit.cta_group::1.mbarrier::arrive::one.shared::cluster.b64 [%0];" :: "r"(mb) : "memory")
#define TC_FENCE_AFTER()  asm volatile("tcgen05.fence::after_thread_sync;" ::: "memory")
#define TC_FENCE_BEFORE() asm volatile("tcgen05.fence::before_thread_sync;" ::: "memory")
#define TC_WAIT_LD()      asm volatile("tcgen05.wait::ld.sync.aligned;" ::: "memory")

#define TC_LD_X16(r, ta) \
    asm volatile("tcgen05.ld.sync.aligned.32x32b.x16.b32 " \
        "{%0,%1,%2,%3,%4,%5,%6,%7,%8,%9,%10,%11,%12,%13,%14,%15}, [%16];" \
        : "=r"((r)[0]),"=r"((r)[1]),"=r"((r)[2]),"=r"((r)[3]), \
          "=r"((r)[4]),"=r"((r)[5]),"=r"((r)[6]),"=r"((r)[7]), \
          "=r"((r)[8]),"=r"((r)[9]),"=r"((r)[10]),"=r"((r)[11]), \
          "=r"((r)[12]),"=r"((r)[13]),"=r"((r)[14]),"=r"((r)[15]) \
        : "r"(ta))

// SW128 K-major SMEM descriptor
__device__ __forceinline__ uint64_t make_desc(uint32_t addr) {
    const uint64_t base =
        (uint64_t(2) << 61) | (uint64_t(1) << 46) | (uint64_t(64) << 32) | (uint64_t(1) << 16);
    return base | ((uint64_t)(addr >> 4) & 0x3FFF);
}
__device__ __forceinline__ void mma_bf16_ss(uint32_t d, uint64_t ad, uint64_t bd,
                                            uint32_t idesc, uint32_t en) {
    asm volatile("{\n\t.reg .pred p;\n\tsetp.ne.u32 p, %4, 0;\n\t"
        "tcgen05.mma.cta_group::1.kind::f16 [%0], %1, %2, %3, {%5,%5,%5,%5}, p;\n\t}"
        :: "r"(d), "l"(ad), "l"(bd), "r"(idesc), "r"(en), "r"(0u) : "memory");
}
// f32x2 packed math
#define FMA2(d, a, b, c) asm("fma.rn.f32x2 %0, %1, %2, %3;" : "=l"(d) : "l"(a), "l"(b), "l"(c))
#define ADD2(d, a, b)    asm("add.rn.f32x2 %0, %1, %2;"     : "=l"(d) : "l"(a), "l"(b))
#define MUL2(d, a, b)    asm("mul.rn.f32x2 %0, %1, %2;"     : "=l"(d) : "l"(a), "l"(b))
#define PACK2(d, lo, hi)  asm("mov.b64 %0, {%1, %2};" : "=l"(d) : "r"(lo), "r"(hi))
#define UNPACK2(lo, hi, s) asm("mov.b64 {%0, %1}, %2;" : "=r"(lo), "=r"(hi) : "l"(s))
#endif  // HAS_TC

// idesc: F32 accum, BF16 a/b, N=64, M=128
#define IDESC ((1u << 4) | (1u << 7) | (1u << 10) | ((BRN / 8) << 17) | ((128 / 16) << 24))

// SMEM layout — ALL offsets relative to the in-kernel 1024-ALIGNED base.
#define SM_TMEMP 0
#define SM_FULLB 16          // 3 x 8B
#define SM_EMPTYB 48         // 3 x 8B
#define SM_DONE 80
#define SM_LAST 96           // last-CTA flag (int)
#define SROT_OFF 128         // 16*12 floats = 768B
#define SQ_OFF 896           // 3*64 floats
#define RED_OFF 1664         // 8*16 floats
#define STAGE0 3072
#define STAGE_BYTES 49152    // AHI 16K + ALO 16K + BHI 8K + BLO 8K
#define AHI_OFF(s) (STAGE0 + (s) * STAGE_BYTES)
#define ALO_OFF(s) (AHI_OFF(s) + 16384)
#define BHI_OFF(s) (AHI_OFF(s) + 32768)
#define BLO_OFF(s) (AHI_OFF(s) + 40960)
// +1024 slack so we can align the dynamic base up to 1024 in-kernel.
#define FUSED_SMEM (STAGE0 + NSTAGE * STAGE_BYTES + 1024)   // 151552

__device__ __forceinline__ uint32_t swz(uint32_t off) { return off ^ ((off >> 3) & 0x70); }
__device__ __forceinline__ uint32_t packbf2(__nv_bfloat162 v) {
    return *reinterpret_cast<uint32_t*>(&v);
}

// ---------------------------------------------------------------------------
// Fused kernel: QR + GEMM (tcgen05, bf16 hi/lo split) + energy epilogue
// + last-CTA final reduction.  grid = (16 rtiles, 8 b), 256 threads.
// ---------------------------------------------------------------------------
__global__ void __launch_bounds__(256, 1) fused_energy(
    const float* __restrict__ lig_feat,
    const float* __restrict__ rec_feat,
    const float* __restrict__ lig_coord,
    const float* __restrict__ rec_coord,
    const float* __restrict__ pre_rot,
    const float* __restrict__ trans,
    const int* __restrict__ ligc,
    const int* __restrict__ recc,
    float* __restrict__ out) {
    extern __shared__ char smraw[];
    // Re-align the dynamic smem base to 1024B: SW128 swizzle + MMA descriptors
    // require atom-aligned tile bases, independent of compiler smem placement.
    const uint32_t sbraw = smem_u32(smraw);
    const uint32_t sb = (sbraw + 1023u) & ~1023u;
    char* sm = smraw + (sb - sbraw);

    const int tid = threadIdx.x;
    const int b = blockIdx.y;
    const int rtile = blockIdx.x;
    const int r0 = rtile * BRN;
    const int RS = NE * NF;                // 2560

    float* s_rot = (float*)(sm + SROT_OFF);
    float* s_qx = (float*)(sm + SQ_OFF);
    float* s_qy = s_qx + 64;
    float* s_qz = s_qx + 128;
    float* s_red = (float*)(sm + RED_OFF);
    volatile int* s_last = (volatile int*)(sm + SM_LAST);

    // ---- Phase 0: QR (LAPACK convention) for 16 timesteps + neg rec coords
    if (tid < NT) {
        const int t = tid;
        const float* A0 = pre_rot + (b * NT + t) * 9;
        float a00 = A0[0], a01 = A0[1], a02 = A0[2];
        float a10 = A0[3], a11 = A0[4], a12 = A0[5];
        float a20 = A0[6], a21 = A0[7], a22 = A0[8];
        float v1 = 0.f, v2 = 0.f, tau0 = 0.f;
        float xn2 = a10 * a10 + a20 * a20;
        if (xn2 > 0.f) {
            float beta = -copysignf(sqrtf(a00 * a00 + xn2), a00);
            tau0 = (beta - a00) / beta;
            float inv = 1.f / (a00 - beta);
            v1 = a10 * inv; v2 = a20 * inv;
            float w1 = a01 + v1 * a11 + v2 * a21;
            a01 -= tau0 * w1; a11 -= tau0 * v1 * w1; a21 -= tau0 * v2 * w1;
            float w2 = a02 + v1 * a12 + v2 * a22;
            a02 -= tau0 * w2; a12 -= tau0 * v1 * w2; a22 -= tau0 * v2 * w2;
        }
        float u2 = 0.f, tau1 = 0.f;
        if (a21 != 0.f) {
            float beta1 = -copysignf(sqrtf(a11 * a11 + a21 * a21), a11);
            tau1 = (beta1 - a11) / beta1;
            u2 = a21 / (a11 - beta1);
        }
        float H0m[3][3] = {
            {1.f - tau0, -tau0 * v1, -tau0 * v2},
            {-tau0 * v1, 1.f - tau0 * v1 * v1, -tau0 * v1 * v2},
            {-tau0 * v2, -tau0 * v1 * v2, 1.f - tau0 * v2 * v2}};
        float H1m[3][3] = {
            {1.f, 0.f, 0.f},
            {0.f, 1.f - tau1, -tau1 * u2},
            {0.f, -tau1 * u2, 1.f - tau1 * u2 * u2}};
#pragma unroll
        for (int i = 0; i < 3; i++)
#pragma unroll
            for (int jj = 0; jj < 3; jj++)
                s_rot[t * 12 + i * 3 + jj] =
                    H0m[i][0] * H1m[0][jj] + H0m[i][1] * H1m[1][jj] + H0m[i][2] * H1m[2][jj];
        s_rot[t * 12 + 9]  = trans[(b * NT + t) * 3 + 0];
        s_rot[t * 12 + 10] = trans[(b * NT + t) * 3 + 1];
        s_rot[t * 12 + 11] = trans[(b * NT + t) * 3 + 2];
    }
    if (tid >= 64 && tid < 128) {
        int r = r0 + (tid - 64);
        s_qx[tid - 64] = -rec_coord[((size_t)b * NR + r) * 3 + 0];
        s_qy[tid - 64] = -rec_coord[((size_t)b * NR + r) * 3 + 1];
        s_qz[tid - 64] = -rec_coord[((size_t)b * NR + r) * 3 + 2];
    }

    const int lc = __ldg(&ligc[b]);
    const int rc = __ldg(&recc[b]);
    const int lane = tid & 31;
    const int w = tid >> 5;

#if HAS_TC
    if (tid == 0) {
#pragma unroll
        for (int s = 0; s < NSTAGE; s++) {
            MBAR_INIT(sb + SM_FULLB + 8 * s, 256);
            MBAR_INIT(sb + SM_EMPTYB + 8 * s, 1);
        }
        MBAR_INIT(sb + SM_DONE, 1);
    }
    if (w == 0) {
        TC_ALLOC(sb + SM_TMEMP, 512);
        TC_RELINQ();
    }
    __syncthreads();
    uint32_t tmem;
    asm volatile("ld.shared.b32 %0, [%1];" : "=r"(tmem) : "r"(sb + SM_TMEMP));

    const float* Abase = lig_feat + (size_t)b * NL * RS;
    const float* Bbase = rec_feat + ((size_t)b * NR + r0) * RS;

    // per-thread invariant offsets (A: 8 rows stride 16; B: first 4)
    size_t aoff[8];
    uint32_t soA[8];
#pragma unroll
    for (int i = 0; i < 8; i++) {
        int row = (tid >> 4) + 16 * i;
        aoff[i] = (size_t)row * RS + ((tid & 15) << 2);
        soA[i] = swz((uint32_t)row * 128 + ((tid & 15) << 3));
    }

    float4 pa0[8], pb0[4], pa1[8], pb1[4];

    // prologue: prefetch iter 0
    {
        const float* Ae = Abase;   // e=0, kc=0
        const float* Be = Bbase;
#pragma unroll
        for (int i = 0; i < 8; i++) pa0[i] = *(const float4*)(Ae + aoff[i]);
#pragma unroll
        for (int i = 0; i < 4; i++) pb0[i] = *(const float4*)(Be + aoff[i]);
    }

#define CVT_PAIR(V, HDST, LDST, SO)                                               \
    do {                                                                          \
        float4 v = (V);                                                           \
        __nv_bfloat162 h01 = __floats2bfloat162_rn(v.x, v.y);                     \
        __nv_bfloat162 h23 = __floats2bfloat162_rn(v.z, v.w);                     \
        float2 f01 = __bfloat1622float2(h01);                                     \
        float2 f23 = __bfloat1622float2(h23);                                     \
        __nv_bfloat162 l01 = __floats2bfloat162_rn(v.x - f01.x, v.y - f01.y);     \
        __nv_bfloat162 l23 = __floats2bfloat162_rn(v.z - f23.x, v.w - f23.y);     \
        *(uint2*)((HDST) + (SO)) = make_uint2(packbf2(h01), packbf2(h23));        \
        *(uint2*)((LDST) + (SO)) = make_uint2(packbf2(l01), packbf2(l23));        \
    } while (0)

#define STEP(ITER, CA, CB, NA, NB_)                                               \
    {                                                                             \
        const int iter_ = (ITER);                                                 \
        if (iter_ + 1 < NITER) {                                                  \
            const int nx = iter_ + 1;                                             \
            const float* An = Abase + (nx >> 3) * NF + (nx & 7) * BKF;            \
            const float* Bn = Bbase + (nx >> 3) * NF + (nx & 7) * BKF;            \
            _Pragma("unroll")                                                     \
            for (int i = 0; i < 8; i++) NA[i] = *(const float4*)(An + aoff[i]);   \
            _Pragma("unroll")                                                     \
            for (int i = 0; i < 4; i++) NB_[i] = *(const float4*)(Bn + aoff[i]);  \
        }                                                                         \
        const int k_ = iter_ / 3;                                                 \
        const int s_ = iter_ - 3 * k_;                                            \
        MBAR_WAIT(sb + SM_EMPTYB + 8 * s_, (k_ & 1) ^ 1);                         \
        char* ah_ = sm + AHI_OFF(s_);                                             \
        char* al_ = sm + ALO_OFF(s_);                                             \
        _Pragma("unroll")                                                         \
        for (int i = 0; i < 8; i++) CVT_PAIR(CA[i], ah_, al_, soA[i]);            \
        char* bh_ = sm + BHI_OFF(s_);                                             \
        char* bl_ = sm + BLO_OFF(s_);                                             \
        _Pragma("unroll")                                                         \
        for (int i = 0; i < 4; i++) CVT_PAIR(CB[i], bh_, bl_, soA[i]);            \
        FENCE_ASYNC_SHARED();                                                     \
        MBAR_ARRIVE(sb + SM_FULLB + 8 * s_);                                      \
        if (tid == 0) {                                                           \
            MBAR_WAIT(sb + SM_FULLB + 8 * s_, k_ & 1);                            \
            uint64_t dah = make_desc(sb + AHI_OFF(s_));                           \
            uint64_t dal = make_desc(sb + ALO_OFF(s_));                           \
            uint64_t dbh = make_desc(sb + BHI_OFF(s_));                           \
            uint64_t dbl = make_desc(sb + BLO_OFF(s_));                           \
            uint32_t dcol = tmem + (iter_ >> 3) * 64;                             \
            const int kc_ = iter_ & 7;                                            \
            _Pragma("unroll")                                                     \
            for (int ks = 0; ks < 4; ks++) {                                      \
                uint64_t o = ks * 2;                                              \
                mma_bf16_ss(dcol, dah + o, dbh + o, IDESC, !(kc_ == 0 && ks == 0)); \
                mma_bf16_ss(dcol, dah + o, dbl + o, IDESC, 1u);                   \
                mma_bf16_ss(dcol, dal + o, dbh + o, IDESC, 1u);                   \
            }                                                                     \
            TC_COMMIT(sb + SM_EMPTYB + 8 * s_);                                   \
        }                                                                         \
    }

    for (int it2 = 0; it2 < NITER; it2 += 2) {
        STEP(it2, pa0, pb0, pa1, pb1);
        STEP(it2 + 1, pa1, pb1, pa0, pb0);
    }
#undef STEP
#undef CVT_PAIR

    if (tid == 0) TC_COMMIT(sb + SM_DONE);
    MBAR_WAIT(sb + SM_DONE, 0);
    TC_FENCE_AFTER();

    // ---- Phase 2: energy epilogue (f32x2 packed over r-pairs)
    const int l = (w & 3) * 32 + lane;
    const int rhalf = w >> 2;
    const bool lok = l < lc;
    const float xl = lig_coord[((size_t)b * NL + l) * 3 + 0];
    const float yl = lig_coord[((size_t)b * NL + l) * 3 + 1];
    const float zl = lig_coord[((size_t)b * NL + l) * 3 + 2];

    uint64_t acc2[NT];
#pragma unroll
    for (int t = 0; t < NT; t++) acc2[t] = 0ull;
    uint64_t eps2;
    PACK2(eps2, __float_as_uint(1e-12f), __float_as_uint(1e-12f));

#pragma unroll
    for (int c = 0; c < 2; c++) {
        const int colbase = rhalf * 32 + c * 16;
        uint32_t ar[NE][16];
#pragma unroll
        for (int e = 0; e < NE; e++) {
            TC_LD_X16(ar[e], tmem + e * 64 + colbase);
        }
        TC_WAIT_LD();
        uint64_t A2[NE][8];
        const int rgbase = r0 + colbase;
#pragma unroll
        for (int e = 0; e < NE; e++)
#pragma unroll
            for (int j = 0; j < 8; j++) {
                uint32_t v0 = (lok && (rgbase + 2 * j)     < rc) ? ar[e][2 * j]     : 0u;
                uint32_t v1 = (lok && (rgbase + 2 * j + 1) < rc) ? ar[e][2 * j + 1] : 0u;
                PACK2(A2[e][j], v0, v1);
            }
        const uint64_t* nqx = (const uint64_t*)(s_qx + colbase);
        const uint64_t* nqy = (const uint64_t*)(s_qy + colbase);
        const uint64_t* nqz = (const uint64_t*)(s_qz + colbase);
#pragma unroll
        for (int t = 0; t < NT; t++) {
            const float* Rt = s_rot + t * 12;
            float px = fmaf(Rt[0], xl, fmaf(Rt[1], yl, fmaf(Rt[2], zl, Rt[9])));
            float py = fmaf(Rt[3], xl, fmaf(Rt[4], yl, fmaf(Rt[5], zl, Rt[10])));
            float pz = fmaf(Rt[6], xl, fmaf(Rt[7], yl, fmaf(Rt[8], zl, Rt[11])));
            uint64_t px2, py2, pz2;
            PACK2(px2, __float_as_uint(px), __float_as_uint(px));
            PACK2(py2, __float_as_uint(py), __float_as_uint(py));
            PACK2(pz2, __float_as_uint(pz), __float_as_uint(pz));
            uint64_t a = acc2[t];
#pragma unroll
            for (int j = 0; j < 8; j++) {
                uint64_t dx, dy, dz, d2, t1, t2;
                ADD2(dx, px2, nqx[j]);
                ADD2(dy, py2, nqy[j]);
                ADD2(dz, pz2, nqz[j]);
                FMA2(t1, dz, dz, eps2);
                FMA2(t2, dy, dy, t1);
                FMA2(d2, dx, dx, t2);
                uint32_t lo, hi;
                UNPACK2(lo, hi, d2);
                float ia = rsqrtf(__uint_as_float(lo));
                float ib = rsqrtf(__uint_as_float(hi));
                uint64_t inv, inv2, inv3, dd;
                PACK2(inv, __float_as_uint(ia), __float_as_uint(ib));
                MUL2(inv2, inv, inv);
                MUL2(inv3, inv2, inv);
                MUL2(dd, d2, inv);
                FMA2(a, A2[0][j], inv3, a);
                FMA2(a, A2[1][j], inv2, a);
                FMA2(a, A2[2][j], inv, a);
                FMA2(a, A2[3][j], dd, a);
                FMA2(a, A2[4][j], d2, a);
            }
            acc2[t] = a;
        }
    }
    TC_FENCE_BEFORE();
    __syncthreads();
    if (w == 0) TC_DEALLOC(tmem, 512);

    float accf[NT];
#pragma unroll
    for (int t = 0; t < NT; t++) {
        uint32_t lo, hi;
        UNPACK2(lo, hi, acc2[t]);
        accf[t] = __uint_as_float(lo) + __uint_as_float(hi);
    }

#else  // ------------------------- SIMT fallback (non-'a' pass) -------------
    __syncthreads();
    const int g = tid >> 2;
    const int j4 = tid & 3;
    const int r = r0 + g;
    const bool rok = r < rc;
    const float qx = rec_coord[((size_t)b * NR + r) * 3 + 0];
    const float qy = rec_coord[((size_t)b * NR + r) * 3 + 1];
    const float qz = rec_coord[((size_t)b * NR + r) * 3 + 2];
    float accf[NT];
#pragma unroll
    for (int t = 0; t < NT; t++) accf[t] = 0.f;

    for (int l = 0; l < NL; l++) {
        float dot[NE];
#pragma unroll
        for (int e = 0; e < NE; e++) dot[e] = 0.f;
        if (l < lc && rok) {
            const float* Arow = lig_feat + ((size_t)b * NL + l) * (NE * NF);
            const float* Brow = rec_feat + ((size_t)b * NR + r) * (NE * NF);
#pragma unroll
            for (int e = 0; e < NE; e++) {
                float sacc = 0.f;
                for (int f = j4 * 4; f < NF; f += 16) {
                    float4 av = *(const float4*)(Arow + e * NF + f);
                    float4 bv = *(const float4*)(Brow + e * NF + f);
                    sacc += av.x * bv.x + av.y * bv.y + av.z * bv.z + av.w * bv.w;
                }
                dot[e] = sacc;
            }
        }
#pragma unroll
        for (int e = 0; e < NE; e++) {
            dot[e] += __shfl_xor_sync(0xffffffffu, dot[e], 1);
            dot[e] += __shfl_xor_sync(0xffffffffu, dot[e], 2);
        }
        float xl = lig_coord[((size_t)b * NL + l) * 3 + 0];
        float yl = lig_coord[((size_t)b * NL + l) * 3 + 1];
        float zl = lig_coord[((size_t)b * NL + l) * 3 + 2];
        for (int t = j4; t < NT; t += 4) {
            const float* Rt = s_rot + t * 12;
            float px = fmaf(Rt[0], xl, fmaf(Rt[1], yl, fmaf(Rt[2], zl, Rt[9])));
            float py = fmaf(Rt[3], xl, fmaf(Rt[4], yl, fmaf(Rt[5], zl, Rt[10])));
            float pz = fmaf(Rt[6], xl, fmaf(Rt[7], yl, fmaf(Rt[8], zl, Rt[11])));
            float dx = px - qx, dy = py - qy, dz = pz - qz;
            float d2 = fmaf(dx, dx, fmaf(dy, dy, dz * dz));
            d2 = fmaxf(d2, 1e-12f);
            float inv = rsqrtf(d2);
            float inv2 = inv * inv;
            float inv3 = inv2 * inv;
            float d = d2 * inv;
            accf[t] += fmaf(dot[0], inv3, fmaf(dot[1], inv2,
                          fmaf(dot[2], inv, fmaf(dot[3], d, dot[4] * d2))));
        }
    }
#endif

    // ---- common block reduction -> g_part[b][rtile][t]
#pragma unroll
    for (int t = 0; t < NT; t++) {
#pragma unroll
        for (int off = 16; off > 0; off >>= 1)
            accf[t] += __shfl_xor_sync(0xffffffffu, accf[t], off);
    }
    if (lane == 0) {
#pragma unroll
        for (int t = 0; t < NT; t++) s_red[w * NT + t] = accf[t];
    }
    __syncthreads();
    if (tid < NT) {
        float s = 0.f;
#pragma unroll
        for (int ww = 0; ww < 8; ww++) s += s_red[ww * NT + tid];
        __stcg(&g_part[(b * 16 + rtile) * NT + tid], s);   // L1-bypass write
    }
    // release: every thread fences, then CTA-wide sync, then one atomic
    __threadfence();
    __syncthreads();

    // ---- last CTA reduces g_part -> out (modulo counter: graph-replay safe)
    if (tid == 0) {
        unsigned old = atomicAdd(&g_ctr, 1u);
        *s_last = ((old & 127u) == 127u) ? 1 : 0;   // grid = 128 CTAs
    }
    __syncthreads();
    if (*s_last) {
        __threadfence();   // acquire after observing all 128 increments
        if (tid < NB * NT) {
            int bb = tid >> 4, t = tid & 15;
            float ssum = 0.f;
#pragma unroll
            for (int rt = 0; rt < 16; rt++)
                ssum += __ldcg(&g_part[(bb * 16 + rt) * NT + t]);   // L1-bypass read
            out[bb * NT + t] = ssum;
        }
    }
}

// ---------------------------------------------------------------------------
extern "C" void kernel_launch(void* const* d_in, const int* in_sizes, int n_in,
                              void* d_out, int out_size) {
    (void)in_sizes; (void)n_in; (void)out_size;
    const float* lig_feat   = (const float*)d_in[0];
    const float* rec_feat   = (const float*)d_in[1];
    const float* lig_coord  = (const float*)d_in[2];
    const float* rec_coord  = (const float*)d_in[3];
    const float* pre_rot    = (const float*)d_in[4];
    const float* trans      = (const float*)d_in[5];
    const int*   lig_counts = (const int*)d_in[6];
    const int*   rec_counts = (const int*)d_in[7];
    float* out = (float*)d_out;

    cudaFuncSetAttribute(fused_energy, cudaFuncAttributeMaxDynamicSharedMemorySize, FUSED_SMEM);

    dim3 g1(16, NB);
    fused_energy<<<g1, 256, FUSED_SMEM>>>(lig_feat, rec_feat, lig_coord, rec_coord,
                                          pre_rot, trans, lig_counts, rec_counts, out);
}

// round 8
// speedup vs baseline: 2.9443x; 1.0947x over previous
#include <cuda_runtime.h>
#include <cuda_bf16.h>
#include <math.h>
#include <stdint.h>

#define NB 8
#define NT 16
#define NL 128
#define NR 1024
#define NE 5
#define NF 512

#define BRN 64            // r-tile per CTA (MMA N)
#define BKF 64            // fp32 K per chunk
#define NITER (NE * (NF / BKF))   // 40
#define NSTAGE 3
#define NTHR 512

#if defined(__CUDA_ARCH__) && (defined(__CUDA_ARCH_FEAT_SM103_ALL) || defined(__CUDA_ARCH_FEAT_SM100_ALL))
#define HAS_TC 1
#else
#define HAS_TC 0
#endif

__device__ float g_part[NB * 16 * NT];   // [b][rtile][t]
__device__ unsigned int g_ctr;

// ---------------------------------------------------------------- helpers
__device__ __forceinline__ uint32_t smem_u32(const void* p) {
    uint32_t a;
    asm("{ .reg .u64 t; cvta.to.shared.u64 t, %1; cvt.u32.u64 %0, t; }" : "=r"(a) : "l"(p));
    return a;
}

#if HAS_TC
#define MBAR_INIT(a, n) asm volatile("mbarrier.init.shared.b64 [%0], %1;" :: "r"(a), "r"(n) : "memory")
#define MBAR_ARRIVE(a)  asm volatile("mbarrier.arrive.shared.b64 _, [%0];" :: "r"(a) : "memory")
#define MBAR_WAIT(a, ph) do {                                                     \
    uint32_t _m = (a), _p = (ph), _d;                                             \
    asm volatile("{\n\t.reg .pred p;\n\t"                                         \
        "mbarrier.try_wait.parity.acquire.cta.shared::cta.b64 p, [%1], %2;\n\t"   \
        "selp.b32 %0, 1, 0, p;\n\t}" : "=r"(_d) : "r"(_m), "r"(_p) : "memory");   \
    if (!_d) {                                                                    \
        asm volatile("{\n\t.reg .pred P1;\n\tW%=:\n\t"                            \
            "mbarrier.try_wait.parity.acquire.cta.shared::cta.b64 P1, [%0], %1, 0x989680;\n\t" \
            "@P1 bra.uni D%=;\n\tbra.uni W%=;\n\tD%=:\n\t}"                       \
            :: "r"(_m), "r"(_p) : "memory");                                      \
    }                                                                             \
} while (0)
#define FENCE_ASYNC_SHARED() asm volatile("fence.proxy.async.shared::cta;" ::: "memory")
#define TC_ALLOC(sm_, n)  asm volatile("tcgen05.alloc.cta_group::1.sync.aligned.shared::cta.b32 [%0], %1;" :: "r"(sm_), "r"(n) : "memory")
#define TC_DEALLOC(t, n)  asm volatile("tcgen05.dealloc.cta_group::1.sync.aligned.b32 %0, %1;" :: "r"(t), "r"(n))
#define TC_RELINQ()       asm volatile("tcgen05.relinquish_alloc_permit.cta_group::1.sync.aligned;")
#define TC_COMMIT(mb)     asm volatile("tcgen05.commit.cta_group::1.mbarrier::arrive::one.shared::cluster.b64 [%0];" :: "r"(mb) : "memory")
#define TC_FENCE_AFTER()  asm volatile("tcgen05.fence::after_thread_sync;" ::: "memory")
#define TC_FENCE_BEFORE() asm volatile("tcgen05.fence::before_thread_sync;" ::: "memory")
#define TC_WAIT_LD()      asm volatile("tcgen05.wait::ld.sync.aligned;" ::: "memory")

#define TC_LD_X8(r, ta) \
    asm volatile("tcgen05.ld.sync.aligned.32x32b.x8.b32 " \
        "{%0,%1,%2,%3,%4,%5,%6,%7}, [%8];" \
        : "=r"((r)[0]),"=r"((r)[1]),"=r"((r)[2]),"=r"((r)[3]), \
          "=r"((r)[4]),"=r"((r)[5]),"=r"((r)[6]),"=r"((r)[7]) \
        : "r"(ta))

__device__ __forceinline__ uint64_t make_desc(uint32_t addr) {
    const uint64_t base =
        (uint64_t(2) << 61) | (uint64_t(1) << 46) | (uint64_t(64) << 32) | (uint64_t(1) << 16);
    return base | ((uint64_t)(addr >> 4) & 0x3FFF);
}
__device__ __forceinline__ void mma_bf16_ss(uint32_t d, uint64_t ad, uint64_t bd,
                                            uint32_t idesc, uint32_t en) {
    asm volatile("{\n\t.reg .pred p;\n\tsetp.ne.u32 p, %4, 0;\n\t"
        "tcgen05.mma.cta_group::1.kind::f16 [%0], %1, %2, %3, {%5,%5,%5,%5}, p;\n\t}"
        :: "r"(d), "l"(ad), "l"(bd), "r"(idesc), "r"(en), "r"(0u) : "memory");
}
#define FMA2(d, a, b, c) asm("fma.rn.f32x2 %0, %1, %2, %3;" : "=l"(d) : "l"(a), "l"(b), "l"(c))
#define ADD2(d, a, b)    asm("add.rn.f32x2 %0, %1, %2;"     : "=l"(d) : "l"(a), "l"(b))
#define MUL2(d, a, b)    asm("mul.rn.f32x2 %0, %1, %2;"     : "=l"(d) : "l"(a), "l"(b))
#define PACK2(d, lo, hi)  asm("mov.b64 %0, {%1, %2};" : "=l"(d) : "r"(lo), "r"(hi))
#define UNPACK2(lo, hi, s) asm("mov.b64 {%0, %1}, %2;" : "=r"(lo), "=r"(hi) : "l"(s))
#endif  // HAS_TC

#define IDESC ((1u << 4) | (1u << 7) | (1u << 10) | ((BRN / 8) << 17) | ((128 / 16) << 24))

// SMEM layout — relative to in-kernel 1024-aligned base.
#define SM_TMEMP 0
#define SM_FULLB 16
#define SM_EMPTYB 48
#define SM_DONE 80
#define SM_LAST 96
#define SROT_OFF 128
#define SQ_OFF 896
#define RED_OFF 1664          // 16*16 floats = 1024B
#define STAGE0 3072
#define STAGE_BYTES 49152
#define AHI_OFF(s) (STAGE0 + (s) * STAGE_BYTES)
#define ALO_OFF(s) (AHI_OFF(s) + 16384)
#define BHI_OFF(s) (AHI_OFF(s) + 32768)
#define BLO_OFF(s) (AHI_OFF(s) + 40960)
#define FUSED_SMEM (STAGE0 + NSTAGE * STAGE_BYTES + 1024)   // 151552

__device__ __forceinline__ uint32_t swz(uint32_t off) { return off ^ ((off >> 3) & 0x70); }
__device__ __forceinline__ uint32_t packbf2(__nv_bfloat162 v) {
    return *reinterpret_cast<uint32_t*>(&v);
}

// ---------------------------------------------------------------------------
// Fused kernel. grid = (16 rtiles, 8 b), 512 threads (16 warps).
// ---------------------------------------------------------------------------
__global__ void __launch_bounds__(NTHR, 1) fused_energy(
    const float* __restrict__ lig_feat,
    const float* __restrict__ rec_feat,
    const float* __restrict__ lig_coord,
    const float* __restrict__ rec_coord,
    const float* __restrict__ pre_rot,
    const float* __restrict__ trans,
    const int* __restrict__ ligc,
    const int* __restrict__ recc,
    float* __restrict__ out) {
    extern __shared__ char smraw[];
    const uint32_t sbraw = smem_u32(smraw);
    const uint32_t sb = (sbraw + 1023u) & ~1023u;
    char* sm = smraw + (sb - sbraw);

    const int tid = threadIdx.x;
    const int b = blockIdx.y;
    const int rtile = blockIdx.x;
    const int r0 = rtile * BRN;
    const int RS = NE * NF;

    float* s_rot = (float*)(sm + SROT_OFF);
    float* s_qx = (float*)(sm + SQ_OFF);
    float* s_qy = s_qx + 64;
    float* s_qz = s_qx + 128;
    float* s_red = (float*)(sm + RED_OFF);
    volatile int* s_last = (volatile int*)(sm + SM_LAST);

    // ---- Phase 0: QR (LAPACK convention) + neg rec coords
    if (tid < NT) {
        const int t = tid;
        const float* A0 = pre_rot + (b * NT + t) * 9;
        float a00 = A0[0], a01 = A0[1], a02 = A0[2];
        float a10 = A0[3], a11 = A0[4], a12 = A0[5];
        float a20 = A0[6], a21 = A0[7], a22 = A0[8];
        float v1 = 0.f, v2 = 0.f, tau0 = 0.f;
        float xn2 = a10 * a10 + a20 * a20;
        if (xn2 > 0.f) {
            float beta = -copysignf(sqrtf(a00 * a00 + xn2), a00);
            tau0 = (beta - a00) / beta;
            float inv = 1.f / (a00 - beta);
            v1 = a10 * inv; v2 = a20 * inv;
            float w1 = a01 + v1 * a11 + v2 * a21;
            a01 -= tau0 * w1; a11 -= tau0 * v1 * w1; a21 -= tau0 * v2 * w1;
            float w2 = a02 + v1 * a12 + v2 * a22;
            a02 -= tau0 * w2; a12 -= tau0 * v1 * w2; a22 -= tau0 * v2 * w2;
        }
        float u2 = 0.f, tau1 = 0.f;
        if (a21 != 0.f) {
            float beta1 = -copysignf(sqrtf(a11 * a11 + a21 * a21), a11);
            tau1 = (beta1 - a11) / beta1;
            u2 = a21 / (a11 - beta1);
        }
        float H0m[3][3] = {
            {1.f - tau0, -tau0 * v1, -tau0 * v2},
            {-tau0 * v1, 1.f - tau0 * v1 * v1, -tau0 * v1 * v2},
            {-tau0 * v2, -tau0 * v1 * v2, 1.f - tau0 * v2 * v2}};
        float H1m[3][3] = {
            {1.f, 0.f, 0.f},
            {0.f, 1.f - tau1, -tau1 * u2},
            {0.f, -tau1 * u2, 1.f - tau1 * u2 * u2}};
#pragma unroll
        for (int i = 0; i < 3; i++)
#pragma unroll
            for (int jj = 0; jj < 3; jj++)
                s_rot[t * 12 + i * 3 + jj] =
                    H0m[i][0] * H1m[0][jj] + H0m[i][1] * H1m[1][jj] + H0m[i][2] * H1m[2][jj];
        s_rot[t * 12 + 9]  = trans[(b * NT + t) * 3 + 0];
        s_rot[t * 12 + 10] = trans[(b * NT + t) * 3 + 1];
        s_rot[t * 12 + 11] = trans[(b * NT + t) * 3 + 2];
    }
    if (tid >= 64 && tid < 128) {
        int r = r0 + (tid - 64);
        s_qx[tid - 64] = -rec_coord[((size_t)b * NR + r) * 3 + 0];
        s_qy[tid - 64] = -rec_coord[((size_t)b * NR + r) * 3 + 1];
        s_qz[tid - 64] = -rec_coord[((size_t)b * NR + r) * 3 + 2];
    }

    const int lc = __ldg(&ligc[b]);
    const int rc = __ldg(&recc[b]);
    const int lane = tid & 31;
    const int w = tid >> 5;

#if HAS_TC
    if (tid == 0) {
#pragma unroll
        for (int s = 0; s < NSTAGE; s++) {
            MBAR_INIT(sb + SM_FULLB + 8 * s, NTHR);
            MBAR_INIT(sb + SM_EMPTYB + 8 * s, 1);
        }
        MBAR_INIT(sb + SM_DONE, 1);
    }
    if (w == 0) {
        TC_ALLOC(sb + SM_TMEMP, 512);
        TC_RELINQ();
    }
    __syncthreads();
    uint32_t tmem;
    asm volatile("ld.shared.b32 %0, [%1];" : "=r"(tmem) : "r"(sb + SM_TMEMP));

    const float* Abase = lig_feat + (size_t)b * NL * RS;
    const float* Bbase = rec_feat + ((size_t)b * NR + r0) * RS;

    // per-thread invariant offsets: rows (tid>>4)+32i, col (tid&15)
    size_t aoff[4];
    uint32_t soA[4];
#pragma unroll
    for (int i = 0; i < 4; i++) {
        int row = (tid >> 4) + 32 * i;
        aoff[i] = (size_t)row * RS + ((tid & 15) << 2);
        soA[i] = swz((uint32_t)row * 128 + ((tid & 15) << 3));
    }

    float4 pa0[4], pb0[2], pa1[4], pb1[2];
    {
#pragma unroll
        for (int i = 0; i < 4; i++) pa0[i] = *(const float4*)(Abase + aoff[i]);
#pragma unroll
        for (int i = 0; i < 2; i++) pb0[i] = *(const float4*)(Bbase + aoff[i]);
    }

#define CVT_PAIR(V, HDST, LDST, SO)                                               \
    do {                                                                          \
        float4 v = (V);                                                           \
        __nv_bfloat162 h01 = __floats2bfloat162_rn(v.x, v.y);                     \
        __nv_bfloat162 h23 = __floats2bfloat162_rn(v.z, v.w);                     \
        float2 f01 = __bfloat1622float2(h01);                                     \
        float2 f23 = __bfloat1622float2(h23);                                     \
        __nv_bfloat162 l01 = __floats2bfloat162_rn(v.x - f01.x, v.y - f01.y);     \
        __nv_bfloat162 l23 = __floats2bfloat162_rn(v.z - f23.x, v.w - f23.y);     \
        *(uint2*)((HDST) + (SO)) = make_uint2(packbf2(h01), packbf2(h23));        \
        *(uint2*)((LDST) + (SO)) = make_uint2(packbf2(l01), packbf2(l23));        \
    } while (0)

#define STEP(ITER, CA, CB, NA, NB_)                                               \
    {                                                                             \
        const int iter_ = (ITER);                                                 \
        if (iter_ + 1 < NITER) {                                                  \
            const int nx = iter_ + 1;                                             \
            const float* An = Abase + (nx >> 3) * NF + (nx & 7) * BKF;            \
            const float* Bn = Bbase + (nx >> 3) * NF + (nx & 7) * BKF;            \
            _Pragma("unroll")                                                     \
            for (int i = 0; i < 4; i++) NA[i] = *(const float4*)(An + aoff[i]);   \
            _Pragma("unroll")                                                     \
            for (int i = 0; i < 2; i++) NB_[i] = *(const float4*)(Bn + aoff[i]);  \
        }                                                                         \
        const int k_ = iter_ / 3;                                                 \
        const int s_ = iter_ - 3 * k_;                                            \
        MBAR_WAIT(sb + SM_EMPTYB + 8 * s_, (k_ & 1) ^ 1);                         \
        char* ah_ = sm + AHI_OFF(s_);                                             \
        char* al_ = sm + ALO_OFF(s_);                                             \
        _Pragma("unroll")                                                         \
        for (int i = 0; i < 4; i++) CVT_PAIR(CA[i], ah_, al_, soA[i]);            \
        char* bh_ = sm + BHI_OFF(s_);                                             \
        char* bl_ = sm + BLO_OFF(s_);                                             \
        _Pragma("unroll")                                                         \
        for (int i = 0; i < 2; i++) CVT_PAIR(CB[i], bh_, bl_, soA[i]);            \
        FENCE_ASYNC_SHARED();                                                     \
        MBAR_ARRIVE(sb + SM_FULLB + 8 * s_);                                      \
        if (tid == 0) {                                                           \
            MBAR_WAIT(sb + SM_FULLB + 8 * s_, k_ & 1);                            \
            uint64_t dah = make_desc(sb + AHI_OFF(s_));                           \
            uint64_t dal = make_desc(sb + ALO_OFF(s_));                           \
            uint64_t dbh = make_desc(sb + BHI_OFF(s_));                           \
            uint64_t dbl = make_desc(sb + BLO_OFF(s_));                           \
            uint32_t dcol = tmem + (iter_ >> 3) * 64;                             \
            const int kc_ = iter_ & 7;                                            \
            _Pragma("unroll")                                                     \
            for (int ks = 0; ks < 4; ks++) {                                      \
                uint64_t o = ks * 2;                                              \
                mma_bf16_ss(dcol, dah + o, dbh + o, IDESC, !(kc_ == 0 && ks == 0)); \
                mma_bf16_ss(dcol, dah + o, dbl + o, IDESC, 1u);                   \
                mma_bf16_ss(dcol, dal + o, dbh + o, IDESC, 1u);                   \
            }                                                                     \
            TC_COMMIT(sb + SM_EMPTYB + 8 * s_);                                   \
        }                                                                         \
    }

    for (int it2 = 0; it2 < NITER; it2 += 2) {
        STEP(it2, pa0, pb0, pa1, pb1);
        STEP(it2 + 1, pa1, pb1, pa0, pb0);
    }
#undef STEP
#undef CVT_PAIR

    if (tid == 0) TC_COMMIT(sb + SM_DONE);
    MBAR_WAIT(sb + SM_DONE, 0);
    TC_FENCE_AFTER();

    // ---- Phase 2: epilogue. warp w: rows (w&3)*32+lane, cols (w>>2)*16..+15.
    const int l = (w & 3) * 32 + lane;
    const int colq = w >> 2;     // 0..3
    const bool lok = l < lc;
    const float xl = lig_coord[((size_t)b * NL + l) * 3 + 0];
    const float yl = lig_coord[((size_t)b * NL + l) * 3 + 1];
    const float zl = lig_coord[((size_t)b * NL + l) * 3 + 2];

    float accf[NT];
    uint64_t eps2;
    PACK2(eps2, __float_as_uint(1e-12f), __float_as_uint(1e-12f));

#pragma unroll
    for (int tp = 0; tp < 2; tp++) {        // two t-passes of 8 (register relief)
        uint64_t acc2[8];
#pragma unroll
        for (int t = 0; t < 8; t++) acc2[t] = 0ull;
#pragma unroll
        for (int cchunk = 0; cchunk < 2; cchunk++) {
            const int colbase = colq * 16 + cchunk * 8;
            uint64_t A2[NE][4];
            {
                uint32_t ar[8];
                const int rgbase = r0 + colbase;
#pragma unroll
                for (int e = 0; e < NE; e++) {
                    TC_LD_X8(ar, tmem + e * 64 + colbase);
                    TC_WAIT_LD();
#pragma unroll
                    for (int j = 0; j < 4; j++) {
                        uint32_t v0 = (lok && (rgbase + 2 * j)     < rc) ? ar[2 * j]     : 0u;
                        uint32_t v1 = (lok && (rgbase + 2 * j + 1) < rc) ? ar[2 * j + 1] : 0u;
                        PACK2(A2[e][j], v0, v1);
                    }
                }
            }
            const uint64_t* nqx = (const uint64_t*)(s_qx + colbase);
            const uint64_t* nqy = (const uint64_t*)(s_qy + colbase);
            const uint64_t* nqz = (const uint64_t*)(s_qz + colbase);
#pragma unroll
            for (int tt = 0; tt < 8; tt++) {
                const int t = tp * 8 + tt;
                const float* Rt = s_rot + t * 12;
                float px = fmaf(Rt[0], xl, fmaf(Rt[1], yl, fmaf(Rt[2], zl, Rt[9])));
                float py = fmaf(Rt[3], xl, fmaf(Rt[4], yl, fmaf(Rt[5], zl, Rt[10])));
                float pz = fmaf(Rt[6], xl, fmaf(Rt[7], yl, fmaf(Rt[8], zl, Rt[11])));
                uint64_t px2, py2, pz2;
                PACK2(px2, __float_as_uint(px), __float_as_uint(px));
                PACK2(py2, __float_as_uint(py), __float_as_uint(py));
                PACK2(pz2, __float_as_uint(pz), __float_as_uint(pz));
                uint64_t a = acc2[tt];
#pragma unroll
                for (int j = 0; j < 4; j++) {
                    uint64_t dx, dy, dz, d2, t1, t2;
                    ADD2(dx, px2, nqx[j]);
                    ADD2(dy, py2, nqy[j]);
                    ADD2(dz, pz2, nqz[j]);
                    FMA2(t1, dz, dz, eps2);
                    FMA2(t2, dy, dy, t1);
                    FMA2(d2, dx, dx, t2);
                    uint32_t lo, hi;
                    UNPACK2(lo, hi, d2);
                    float ia = rsqrtf(__uint_as_float(lo));
                    float ib = rsqrtf(__uint_as_float(hi));
                    uint64_t inv, inv2, inv3, dd;
                    PACK2(inv, __float_as_uint(ia), __float_as_uint(ib));
                    MUL2(inv2, inv, inv);
                    MUL2(inv3, inv2, inv);
                    MUL2(dd, d2, inv);
                    FMA2(a, A2[0][j], inv3, a);
                    FMA2(a, A2[1][j], inv2, a);
                    FMA2(a, A2[2][j], inv, a);
                    FMA2(a, A2[3][j], dd, a);
                    FMA2(a, A2[4][j], d2, a);
                }
                acc2[tt] = a;
            }
        }
#pragma unroll
        for (int tt = 0; tt < 8; tt++) {
            uint32_t lo, hi;
            UNPACK2(lo, hi, acc2[tt]);
            accf[tp * 8 + tt] = __uint_as_float(lo) + __uint_as_float(hi);
        }
    }
    TC_FENCE_BEFORE();
    __syncthreads();
    if (w == 0) TC_DEALLOC(tmem, 512);

#else  // ------------------------- SIMT fallback (non-'a' pass) -------------
    __syncthreads();
    const int g = tid >> 3;          // 0..63 -> r index
    const int j8 = tid & 7;
    const int r = r0 + g;
    const bool rok = r < rc;
    const float qx = rec_coord[((size_t)b * NR + r) * 3 + 0];
    const float qy = rec_coord[((size_t)b * NR + r) * 3 + 1];
    const float qz = rec_coord[((size_t)b * NR + r) * 3 + 2];
    float accf[NT];
#pragma unroll
    for (int t = 0; t < NT; t++) accf[t] = 0.f;

    for (int l = 0; l < NL; l++) {
        float dot[NE];
#pragma unroll
        for (int e = 0; e < NE; e++) dot[e] = 0.f;
        if (l < lc && rok) {
            const float* Arow = lig_feat + ((size_t)b * NL + l) * (NE * NF);
            const float* Brow = rec_feat + ((size_t)b * NR + r) * (NE * NF);
#pragma unroll
            for (int e = 0; e < NE; e++) {
                float sacc = 0.f;
                for (int f = j8 * 4; f < NF; f += 32) {
                    float4 av = *(const float4*)(Arow + e * NF + f);
                    float4 bv = *(const float4*)(Brow + e * NF + f);
                    sacc += av.x * bv.x + av.y * bv.y + av.z * bv.z + av.w * bv.w;
                }
                dot[e] = sacc;
            }
        }
#pragma unroll
        for (int e = 0; e < NE; e++) {
            dot[e] += __shfl_xor_sync(0xffffffffu, dot[e], 1);
            dot[e] += __shfl_xor_sync(0xffffffffu, dot[e], 2);
            dot[e] += __shfl_xor_sync(0xffffffffu, dot[e], 4);
        }
        float xl = lig_coord[((size_t)b * NL + l) * 3 + 0];
        float yl = lig_coord[((size_t)b * NL + l) * 3 + 1];
        float zl = lig_coord[((size_t)b * NL + l) * 3 + 2];
        for (int t = j8; t < NT; t += 8) {
            const float* Rt = s_rot + t * 12;
            float px = fmaf(Rt[0], xl, fmaf(Rt[1], yl, fmaf(Rt[2], zl, Rt[9])));
            float py = fmaf(Rt[3], xl, fmaf(Rt[4], yl, fmaf(Rt[5], zl, Rt[10])));
            float pz = fmaf(Rt[6], xl, fmaf(Rt[7], yl, fmaf(Rt[8], zl, Rt[11])));
            float dx = px - qx, dy = py - qy, dz = pz - qz;
            float d2 = fmaf(dx, dx, fmaf(dy, dy, dz * dz));
            d2 = fmaxf(d2, 1e-12f);
            float inv = rsqrtf(d2);
            float inv2 = inv * inv;
            float inv3 = inv2 * inv;
            float d = d2 * inv;
            accf[t] += fmaf(dot[0], inv3, fmaf(dot[1], inv2,
                          fmaf(dot[2], inv, fmaf(dot[3], d, dot[4] * d2))));
        }
    }
#endif

    // ---- common block reduction -> g_part[b][rtile][t]
#pragma unroll
    for (int t = 0; t < NT; t++) {
#pragma unroll
        for (int off = 16; off > 0; off >>= 1)
            accf[t] += __shfl_xor_sync(0xffffffffu, accf[t], off);
    }
    if (lane == 0) {
#pragma unroll
        for (int t = 0; t < NT; t++) s_red[w * NT + t] = accf[t];
    }
    __syncthreads();
    if (tid < NT) {
        float s = 0.f;
#pragma unroll
        for (int ww = 0; ww < 16; ww++) s += s_red[ww * NT + tid];
        __stcg(&g_part[(b * 16 + rtile) * NT + tid], s);
    }
    __threadfence();
    __syncthreads();

    if (tid == 0) {
        unsigned old = atomicAdd(&g_ctr, 1u);
        *s_last = ((old & 127u) == 127u) ? 1 : 0;   // grid = 128 CTAs
    }
    __syncthreads();
    if (*s_last) {
        __threadfence();
        if (tid < NB * NT) {
            int bb = tid >> 4, t = tid & 15;
            float ssum = 0.f;
#pragma unroll
            for (int rt = 0; rt < 16; rt++)
                ssum += __ldcg(&g_part[(bb * 16 + rt) * NT + t]);
            out[bb * NT + t] = ssum;
        }
    }
}

// ---------------------------------------------------------------------------
extern "C" void kernel_launch(void* const* d_in, const int* in_sizes, int n_in,
                              void* d_out, int out_size) {
    (void)in_sizes; (void)n_in; (void)out_size;
    const float* lig_feat   = (const float*)d_in[0];
    const float* rec_feat   = (const float*)d_in[1];
    const float* lig_coord  = (const float*)d_in[2];
    const float* rec_coord  = (const float*)d_in[3];
    const float* pre_rot    = (const float*)d_in[4];
    const float* trans      = (const float*)d_in[5];
    const int*   lig_counts = (const int*)d_in[6];
    const int*   rec_counts = (const int*)d_in[7];
    float* out = (float*)d_out;

    cudaFuncSetAttribute(fused_energy, cudaFuncAttributeMaxDynamicSharedMemorySize, FUSED_SMEM);

    dim3 g1(16, NB);
    fused_energy<<<g1, NTHR, FUSED_SMEM>>>(lig_feat, rec_feat, lig_coord, rec_coord,
                                           pre_rot, trans, lig_counts, rec_counts, out);
}

// round 9
// speedup vs baseline: 3.5043x; 1.1902x over previous
#include <cuda_runtime.h>
#include <cuda_bf16.h>
#include <math.h>
#include <stdint.h>

#define NB 8
#define NT 16
#define NL 128
#define NR 1024
#define NE 5
#define NF 512

#define BRN 64            // r-tile per CTA (MMA N)
#define BKF 64            // fp32 K per chunk
#define NITER (NE * (NF / BKF))   // 40
#define NSTAGE 3
#define NTHR 512

#if defined(__CUDA_ARCH__) && (defined(__CUDA_ARCH_FEAT_SM103_ALL) || defined(__CUDA_ARCH_FEAT_SM100_ALL))
#define HAS_TC 1
#else
#define HAS_TC 0
#endif

__device__ float g_part[NB * 16 * NT];   // [b][rtile][t]
__device__ unsigned int g_ctr;

// ---------------------------------------------------------------- helpers
__device__ __forceinline__ uint32_t smem_u32(const void* p) {
    uint32_t a;
    asm("{ .reg .u64 t; cvta.to.shared.u64 t, %1; cvt.u32.u64 %0, t; }" : "=r"(a) : "l"(p));
    return a;
}

#if HAS_TC
#define MBAR_INIT(a, n) asm volatile("mbarrier.init.shared.b64 [%0], %1;" :: "r"(a), "r"(n) : "memory")
#define MBAR_WAIT(a, ph) do {                                                     \
    uint32_t _m = (a), _p = (ph), _d;                                             \
    asm volatile("{\n\t.reg .pred p;\n\t"                                         \
        "mbarrier.try_wait.parity.acquire.cta.shared::cta.b64 p, [%1], %2;\n\t"   \
        "selp.b32 %0, 1, 0, p;\n\t}" : "=r"(_d) : "r"(_m), "r"(_p) : "memory");   \
    if (!_d) {                                                                    \
        asm volatile("{\n\t.reg .pred P1;\n\tW%=:\n\t"                            \
            "mbarrier.try_wait.parity.acquire.cta.shared::cta.b64 P1, [%0], %1, 0x989680;\n\t" \
            "@P1 bra.uni D%=;\n\tbra.uni W%=;\n\tD%=:\n\t}"                       \
            :: "r"(_m), "r"(_p) : "memory");                                      \
    }                                                                             \
} while (0)
#define FENCE_ASYNC_SHARED() asm volatile("fence.proxy.async.shared::cta;" ::: "memory")
#define TC_ALLOC(sm_, n)  asm volatile("tcgen05.alloc.cta_group::1.sync.aligned.shared::cta.b32 [%0], %1;" :: "r"(sm_), "r"(n) : "memory")
#define TC_DEALLOC(t, n)  asm volatile("tcgen05.dealloc.cta_group::1.sync.aligned.b32 %0, %1;" :: "r"(t), "r"(n))
#define TC_RELINQ()       asm volatile("tcgen05.relinquish_alloc_permit.cta_group::1.sync.aligned;")
#define TC_COMMIT(mb)     asm volatile("tcgen05.commit.cta_group::1.mbarrier::arrive::one.shared::cluster.b64 [%0];" :: "r"(mb) : "memory")
#define TC_FENCE_AFTER()  asm volatile("tcgen05.fence::after_thread_sync;" ::: "memory")
#define TC_FENCE_BEFORE() asm volatile("tcgen05.fence::before_thread_sync;" ::: "memory")
#define TC_WAIT_LD()      asm volatile("tcgen05.wait::ld.sync.aligned;" ::: "memory")

#define TC_LD_X8(r, ta) \
    asm volatile("tcgen05.ld.sync.aligned.32x32b.x8.b32 " \
        "{%0,%1,%2,%3,%4,%5,%6,%7}, [%8];" \
        : "=r"((r)[0]),"=r"((r)[1]),"=r"((r)[2]),"=r"((r)[3]), \
          "=r"((r)[4]),"=r"((r)[5]),"=r"((r)[6]),"=r"((r)[7]) \
        : "r"(ta))

__device__ __forceinline__ uint64_t make_desc(uint32_t addr) {
    const uint64_t base =
        (uint64_t(2) << 61) | (uint64_t(1) << 46) | (uint64_t(64) << 32) | (uint64_t(1) << 16);
    return base | ((uint64_t)(addr >> 4) & 0x3FFF);
}
__device__ __forceinline__ void mma_bf16_ss(uint32_t d, uint64_t ad, uint64_t bd,
                                            uint32_t idesc, uint32_t en) {
    asm volatile("{\n\t.reg .pred p;\n\tsetp.ne.u32 p, %4, 0;\n\t"
        "tcgen05.mma.cta_group::1.kind::f16 [%0], %1, %2, %3, {%5,%5,%5,%5}, p;\n\t}"
        :: "r"(d), "l"(ad), "l"(bd), "r"(idesc), "r"(en), "r"(0u) : "memory");
}
#define FMA2(d, a, b, c) asm("fma.rn.f32x2 %0, %1, %2, %3;" : "=l"(d) : "l"(a), "l"(b), "l"(c))
#define ADD2(d, a, b)    asm("add.rn.f32x2 %0, %1, %2;"     : "=l"(d) : "l"(a), "l"(b))
#define MUL2(d, a, b)    asm("mul.rn.f32x2 %0, %1, %2;"     : "=l"(d) : "l"(a), "l"(b))
#define PACK2(d, lo, hi)  asm("mov.b64 %0, {%1, %2};" : "=l"(d) : "r"(lo), "r"(hi))
#define UNPACK2(lo, hi, s) asm("mov.b64 {%0, %1}, %2;" : "=r"(lo), "=r"(hi) : "l"(s))
#endif  // HAS_TC

#define IDESC ((1u << 4) | (1u << 7) | (1u << 10) | ((BRN / 8) << 17) | ((128 / 16) << 24))

// SMEM layout — relative to in-kernel 1024-aligned base.
#define SM_TMEMP 0
#define SM_EMPTYB 48         // 3 x 8B (empty barriers only)
#define SM_DONE 80
#define SM_LAST 96
#define SROT_OFF 128
#define SQ_OFF 896
#define RED_OFF 1664          // 16*16 floats
#define STAGE0 3072
#define STAGE_BYTES 49152
#define AHI_OFF(s) (STAGE0 + (s) * STAGE_BYTES)
#define ALO_OFF(s) (AHI_OFF(s) + 16384)
#define BHI_OFF(s) (AHI_OFF(s) + 32768)
#define BLO_OFF(s) (AHI_OFF(s) + 40960)
#define FUSED_SMEM (STAGE0 + NSTAGE * STAGE_BYTES + 1024)   // 151552

__device__ __forceinline__ uint32_t swz(uint32_t off) { return off ^ ((off >> 3) & 0x70); }
__device__ __forceinline__ uint32_t packbf2(__nv_bfloat162 v) {
    return *reinterpret_cast<uint32_t*>(&v);
}

// ---------------------------------------------------------------------------
// Fused kernel. grid = (16 rtiles, 8 b), 512 threads (16 warps).
// ---------------------------------------------------------------------------
__global__ void __launch_bounds__(NTHR, 1) fused_energy(
    const float* __restrict__ lig_feat,
    const float* __restrict__ rec_feat,
    const float* __restrict__ lig_coord,
    const float* __restrict__ rec_coord,
    const float* __restrict__ pre_rot,
    const float* __restrict__ trans,
    const int* __restrict__ ligc,
    const int* __restrict__ recc,
    float* __restrict__ out) {
    extern __shared__ char smraw[];
    const uint32_t sbraw = smem_u32(smraw);
    const uint32_t sb = (sbraw + 1023u) & ~1023u;
    char* sm = smraw + (sb - sbraw);

    const int tid = threadIdx.x;
    const int b = blockIdx.y;
    const int rtile = blockIdx.x;
    const int r0 = rtile * BRN;
    const int RS = NE * NF;

    float* s_rot = (float*)(sm + SROT_OFF);
    float* s_qx = (float*)(sm + SQ_OFF);
    float* s_qy = s_qx + 64;
    float* s_qz = s_qx + 128;
    float* s_red = (float*)(sm + RED_OFF);
    volatile int* s_last = (volatile int*)(sm + SM_LAST);

    // ---- Phase 0: QR (LAPACK convention) + neg rec coords
    if (tid < NT) {
        const int t = tid;
        const float* A0 = pre_rot + (b * NT + t) * 9;
        float a00 = A0[0], a01 = A0[1], a02 = A0[2];
        float a10 = A0[3], a11 = A0[4], a12 = A0[5];
        float a20 = A0[6], a21 = A0[7], a22 = A0[8];
        float v1 = 0.f, v2 = 0.f, tau0 = 0.f;
        float xn2 = a10 * a10 + a20 * a20;
        if (xn2 > 0.f) {
            float beta = -copysignf(sqrtf(a00 * a00 + xn2), a00);
            tau0 = (beta - a00) / beta;
            float inv = 1.f / (a00 - beta);
            v1 = a10 * inv; v2 = a20 * inv;
            float w1 = a01 + v1 * a11 + v2 * a21;
            a01 -= tau0 * w1; a11 -= tau0 * v1 * w1; a21 -= tau0 * v2 * w1;
            float w2 = a02 + v1 * a12 + v2 * a22;
            a02 -= tau0 * w2; a12 -= tau0 * v1 * w2; a22 -= tau0 * v2 * w2;
        }
        float u2 = 0.f, tau1 = 0.f;
        if (a21 != 0.f) {
            float beta1 = -copysignf(sqrtf(a11 * a11 + a21 * a21), a11);
            tau1 = (beta1 - a11) / beta1;
            u2 = a21 / (a11 - beta1);
        }
        float H0m[3][3] = {
            {1.f - tau0, -tau0 * v1, -tau0 * v2},
            {-tau0 * v1, 1.f - tau0 * v1 * v1, -tau0 * v1 * v2},
            {-tau0 * v2, -tau0 * v1 * v2, 1.f - tau0 * v2 * v2}};
        float H1m[3][3] = {
            {1.f, 0.f, 0.f},
            {0.f, 1.f - tau1, -tau1 * u2},
            {0.f, -tau1 * u2, 1.f - tau1 * u2 * u2}};
#pragma unroll
        for (int i = 0; i < 3; i++)
#pragma unroll
            for (int jj = 0; jj < 3; jj++)
                s_rot[t * 12 + i * 3 + jj] =
                    H0m[i][0] * H1m[0][jj] + H0m[i][1] * H1m[1][jj] + H0m[i][2] * H1m[2][jj];
        s_rot[t * 12 + 9]  = trans[(b * NT + t) * 3 + 0];
        s_rot[t * 12 + 10] = trans[(b * NT + t) * 3 + 1];
        s_rot[t * 12 + 11] = trans[(b * NT + t) * 3 + 2];
    }
    if (tid >= 64 && tid < 128) {
        int r = r0 + (tid - 64);
        s_qx[tid - 64] = -rec_coord[((size_t)b * NR + r) * 3 + 0];
        s_qy[tid - 64] = -rec_coord[((size_t)b * NR + r) * 3 + 1];
        s_qz[tid - 64] = -rec_coord[((size_t)b * NR + r) * 3 + 2];
    }

    const int lc = __ldg(&ligc[b]);
    const int rc = __ldg(&recc[b]);
    const int lane = tid & 31;
    const int w = tid >> 5;

#if HAS_TC
    if (tid == 0) {
#pragma unroll
        for (int s = 0; s < NSTAGE; s++) MBAR_INIT(sb + SM_EMPTYB + 8 * s, 1);
        MBAR_INIT(sb + SM_DONE, 1);
    }
    if (w == 0) {
        TC_ALLOC(sb + SM_TMEMP, 512);
        TC_RELINQ();
    }
    __syncthreads();
    uint32_t tmem;
    asm volatile("ld.shared.b32 %0, [%1];" : "=r"(tmem) : "r"(sb + SM_TMEMP));

    const float* Abase = lig_feat + (size_t)b * NL * RS;
    const float* Bbase = rec_feat + ((size_t)b * NR + r0) * RS;

    // per-thread invariant offsets: rows (tid>>4)+32i, col (tid&15)
    size_t aoff[4];
    uint32_t soA[4];
#pragma unroll
    for (int i = 0; i < 4; i++) {
        int row = (tid >> 4) + 32 * i;
        aoff[i] = (size_t)row * RS + ((tid & 15) << 2);
        soA[i] = swz((uint32_t)row * 128 + ((tid & 15) << 3));
    }

    float4 pa0[4], pb0[2], pa1[4], pb1[2];
    {
#pragma unroll
        for (int i = 0; i < 4; i++) pa0[i] = *(const float4*)(Abase + aoff[i]);
#pragma unroll
        for (int i = 0; i < 2; i++) pb0[i] = *(const float4*)(Bbase + aoff[i]);
    }

#define CVT_PAIR(V, HDST, LDST, SO)                                               \
    do {                                                                          \
        float4 v = (V);                                                           \
        __nv_bfloat162 h01 = __floats2bfloat162_rn(v.x, v.y);                     \
        __nv_bfloat162 h23 = __floats2bfloat162_rn(v.z, v.w);                     \
        float2 f01 = __bfloat1622float2(h01);                                     \
        float2 f23 = __bfloat1622float2(h23);                                     \
        __nv_bfloat162 l01 = __floats2bfloat162_rn(v.x - f01.x, v.y - f01.y);     \
        __nv_bfloat162 l23 = __floats2bfloat162_rn(v.z - f23.x, v.w - f23.y);     \
        *(uint2*)((HDST) + (SO)) = make_uint2(packbf2(h01), packbf2(h23));        \
        *(uint2*)((LDST) + (SO)) = make_uint2(packbf2(l01), packbf2(l23));        \
    } while (0)

// per-iter protocol: empty-wait -> cvt+STS -> __syncthreads -> tid0: fence+MMA+commit
#define STEP(ITER, CA, CB, NA, NB_)                                               \
    {                                                                             \
        const int iter_ = (ITER);                                                 \
        if (iter_ + 1 < NITER) {                                                  \
            const int nx = iter_ + 1;                                             \
            const float* An = Abase + (nx >> 3) * NF + (nx & 7) * BKF;            \
            const float* Bn = Bbase + (nx >> 3) * NF + (nx & 7) * BKF;            \
            _Pragma("unroll")                                                     \
            for (int i = 0; i < 4; i++) NA[i] = *(const float4*)(An + aoff[i]);   \
            _Pragma("unroll")                                                     \
            for (int i = 0; i < 2; i++) NB_[i] = *(const float4*)(Bn + aoff[i]);  \
        }                                                                         \
        const int k_ = iter_ / 3;                                                 \
        const int s_ = iter_ - 3 * k_;                                            \
        MBAR_WAIT(sb + SM_EMPTYB + 8 * s_, (k_ & 1) ^ 1);                         \
        char* ah_ = sm + AHI_OFF(s_);                                             \
        char* al_ = sm + ALO_OFF(s_);                                             \
        _Pragma("unroll")                                                         \
        for (int i = 0; i < 4; i++) CVT_PAIR(CA[i], ah_, al_, soA[i]);            \
        char* bh_ = sm + BHI_OFF(s_);                                             \
        char* bl_ = sm + BLO_OFF(s_);                                             \
        _Pragma("unroll")                                                         \
        for (int i = 0; i < 2; i++) CVT_PAIR(CB[i], bh_, bl_, soA[i]);            \
        __syncthreads();                                                          \
        if (tid == 0) {                                                           \
            FENCE_ASYNC_SHARED();                                                 \
            uint64_t dah = make_desc(sb + AHI_OFF(s_));                           \
            uint64_t dal = make_desc(sb + ALO_OFF(s_));                           \
            uint64_t dbh = make_desc(sb + BHI_OFF(s_));                           \
            uint64_t dbl = make_desc(sb + BLO_OFF(s_));                           \
            uint32_t dcol = tmem + (iter_ >> 3) * 64;                             \
            const int kc_ = iter_ & 7;                                            \
            _Pragma("unroll")                                                     \
            for (int ks = 0; ks < 4; ks++) {                                      \
                uint64_t o = ks * 2;                                              \
                mma_bf16_ss(dcol, dah + o, dbh + o, IDESC, !(kc_ == 0 && ks == 0)); \
                mma_bf16_ss(dcol, dah + o, dbl + o, IDESC, 1u);                   \
                mma_bf16_ss(dcol, dal + o, dbh + o, IDESC, 1u);                   \
            }                                                                     \
            TC_COMMIT(sb + SM_EMPTYB + 8 * s_);                                   \
        }                                                                         \
    }

    for (int it2 = 0; it2 < NITER; it2 += 2) {
        STEP(it2, pa0, pb0, pa1, pb1);
        STEP(it2 + 1, pa1, pb1, pa0, pb0);
    }
#undef STEP
#undef CVT_PAIR

    if (tid == 0) TC_COMMIT(sb + SM_DONE);
    MBAR_WAIT(sb + SM_DONE, 0);
    TC_FENCE_AFTER();

    // ---- Phase 2: epilogue. warp w: rows (w&3)*32+lane, cols (w>>2)*16..+15.
    const int l = (w & 3) * 32 + lane;
    const int colq = w >> 2;     // 0..3
    const bool lok = l < lc;
    const float xl = lig_coord[((size_t)b * NL + l) * 3 + 0];
    const float yl = lig_coord[((size_t)b * NL + l) * 3 + 1];
    const float zl = lig_coord[((size_t)b * NL + l) * 3 + 2];

    float accf[NT];
    uint64_t eps2;
    PACK2(eps2, __float_as_uint(1e-12f), __float_as_uint(1e-12f));

#pragma unroll
    for (int tp = 0; tp < 2; tp++) {        // two t-passes of 8
        uint64_t acc2[8];
#pragma unroll
        for (int t = 0; t < 8; t++) acc2[t] = 0ull;
#pragma unroll
        for (int cchunk = 0; cchunk < 2; cchunk++) {
            const int colbase = colq * 16 + cchunk * 8;
            uint64_t A2[NE][4];
            {
                uint32_t ar[NE][8];
#pragma unroll
                for (int e = 0; e < NE; e++)
                    TC_LD_X8(ar[e], tmem + e * 64 + colbase);
                TC_WAIT_LD();     // single wait for all 5 loads
                const int rgbase = r0 + colbase;
#pragma unroll
                for (int e = 0; e < NE; e++)
#pragma unroll
                    for (int j = 0; j < 4; j++) {
                        uint32_t v0 = (lok && (rgbase + 2 * j)     < rc) ? ar[e][2 * j]     : 0u;
                        uint32_t v1 = (lok && (rgbase + 2 * j + 1) < rc) ? ar[e][2 * j + 1] : 0u;
                        PACK2(A2[e][j], v0, v1);
                    }
            }
            const uint64_t* nqx = (const uint64_t*)(s_qx + colbase);
            const uint64_t* nqy = (const uint64_t*)(s_qy + colbase);
            const uint64_t* nqz = (const uint64_t*)(s_qz + colbase);
#pragma unroll
            for (int tt = 0; tt < 8; tt++) {
                const int t = tp * 8 + tt;
                const float* Rt = s_rot + t * 12;
                float px = fmaf(Rt[0], xl, fmaf(Rt[1], yl, fmaf(Rt[2], zl, Rt[9])));
                float py = fmaf(Rt[3], xl, fmaf(Rt[4], yl, fmaf(Rt[5], zl, Rt[10])));
                float pz = fmaf(Rt[6], xl, fmaf(Rt[7], yl, fmaf(Rt[8], zl, Rt[11])));
                uint64_t px2, py2, pz2;
                PACK2(px2, __float_as_uint(px), __float_as_uint(px));
                PACK2(py2, __float_as_uint(py), __float_as_uint(py));
                PACK2(pz2, __float_as_uint(pz), __float_as_uint(pz));
                uint64_t a = acc2[tt];
#pragma unroll
                for (int j = 0; j < 4; j++) {
                    uint64_t dx, dy, dz, d2, t1, t2;
                    ADD2(dx, px2, nqx[j]);
                    ADD2(dy, py2, nqy[j]);
                    ADD2(dz, pz2, nqz[j]);
                    FMA2(t1, dz, dz, eps2);
                    FMA2(t2, dy, dy, t1);
                    FMA2(d2, dx, dx, t2);
                    uint32_t lo, hi;
                    UNPACK2(lo, hi, d2);
                    float ia = rsqrtf(__uint_as_float(lo));
                    float ib = rsqrtf(__uint_as_float(hi));
                    uint64_t inv, inv2, inv3, dd;
                    PACK2(inv, __float_as_uint(ia), __float_as_uint(ib));
                    MUL2(inv2, inv, inv);
                    MUL2(inv3, inv2, inv);
                    MUL2(dd, d2, inv);
                    FMA2(a, A2[0][j], inv3, a);
                    FMA2(a, A2[1][j], inv2, a);
                    FMA2(a, A2[2][j], inv, a);
                    FMA2(a, A2[3][j], dd, a);
                    FMA2(a, A2[4][j], d2, a);
                }
                acc2[tt] = a;
            }
        }
#pragma unroll
        for (int tt = 0; tt < 8; tt++) {
            uint32_t lo, hi;
            UNPACK2(lo, hi, acc2[tt]);
            accf[tp * 8 + tt] = __uint_as_float(lo) + __uint_as_float(hi);
        }
    }
    TC_FENCE_BEFORE();
    __syncthreads();
    if (w == 0) TC_DEALLOC(tmem, 512);

#else  // ------------------------- SIMT fallback (non-'a' pass) -------------
    __syncthreads();
    const int g = tid >> 3;
    const int j8 = tid & 7;
    const int r = r0 + g;
    const bool rok = r < rc;
    const float qx = rec_coord[((size_t)b * NR + r) * 3 + 0];
    const float qy = rec_coord[((size_t)b * NR + r) * 3 + 1];
    const float qz = rec_coord[((size_t)b * NR + r) * 3 + 2];
    float accf[NT];
#pragma unroll
    for (int t = 0; t < NT; t++) accf[t] = 0.f;

    for (int l = 0; l < NL; l++) {
        float dot[NE];
#pragma unroll
        for (int e = 0; e < NE; e++) dot[e] = 0.f;
        if (l < lc && rok) {
            const float* Arow = lig_feat + ((size_t)b * NL + l) * (NE * NF);
            const float* Brow = rec_feat + ((size_t)b * NR + r) * (NE * NF);
#pragma unroll
            for (int e = 0; e < NE; e++) {
                float sacc = 0.f;
                for (int f = j8 * 4; f < NF; f += 32) {
                    float4 av = *(const float4*)(Arow + e * NF + f);
                    float4 bv = *(const float4*)(Brow + e * NF + f);
                    sacc += av.x * bv.x + av.y * bv.y + av.z * bv.z + av.w * bv.w;
                }
                dot[e] = sacc;
            }
        }
#pragma unroll
        for (int e = 0; e < NE; e++) {
            dot[e] += __shfl_xor_sync(0xffffffffu, dot[e], 1);
            dot[e] += __shfl_xor_sync(0xffffffffu, dot[e], 2);
            dot[e] += __shfl_xor_sync(0xffffffffu, dot[e], 4);
        }
        float xl = lig_coord[((size_t)b * NL + l) * 3 + 0];
        float yl = lig_coord[((size_t)b * NL + l) * 3 + 1];
        float zl = lig_coord[((size_t)b * NL + l) * 3 + 2];
        for (int t = j8; t < NT; t += 8) {
            const float* Rt = s_rot + t * 12;
            float px = fmaf(Rt[0], xl, fmaf(Rt[1], yl, fmaf(Rt[2], zl, Rt[9])));
            float py = fmaf(Rt[3], xl, fmaf(Rt[4], yl, fmaf(Rt[5], zl, Rt[10])));
            float pz = fmaf(Rt[6], xl, fmaf(Rt[7], yl, fmaf(Rt[8], zl, Rt[11])));
            float dx = px - qx, dy = py - qy, dz = pz - qz;
            float d2 = fmaf(dx, dx, fmaf(dy, dy, dz * dz));
            d2 = fmaxf(d2, 1e-12f);
            float inv = rsqrtf(d2);
            float inv2 = inv * inv;
            float inv3 = inv2 * inv;
            float d = d2 * inv;
            accf[t] += fmaf(dot[0], inv3, fmaf(dot[1], inv2,
                          fmaf(dot[2], inv, fmaf(dot[3], d, dot[4] * d2))));
        }
    }
#endif

    // ---- common block reduction -> g_part[b][rtile][t]
#pragma unroll
    for (int t = 0; t < NT; t++) {
#pragma unroll
        for (int off = 16; off > 0; off >>= 1)
            accf[t] += __shfl_xor_sync(0xffffffffu, accf[t], off);
    }
    if (lane == 0) {
#pragma unroll
        for (int t = 0; t < NT; t++) s_red[w * NT + t] = accf[t];
    }
    __syncthreads();
    if (tid < NT) {
        float s = 0.f;
#pragma unroll
        for (int ww = 0; ww < 16; ww++) s += s_red[ww * NT + tid];
        __stcg(&g_part[(b * 16 + rtile) * NT + tid], s);
    }
    __threadfence();
    __syncthreads();

    if (tid == 0) {
        unsigned old = atomicAdd(&g_ctr, 1u);
        *s_last = ((old & 127u) == 127u) ? 1 : 0;   // grid = 128 CTAs
    }
    __syncthreads();
    if (*s_last) {
        __threadfence();
        if (tid < NB * NT) {
            int bb = tid >> 4, t = tid & 15;
            float ssum = 0.f;
#pragma unroll
            for (int rt = 0; rt < 16; rt++)
                ssum += __ldcg(&g_part[(bb * 16 + rt) * NT + t]);
            out[bb * NT + t] = ssum;
        }
    }
}

// ---------------------------------------------------------------------------
extern "C" void kernel_launch(void* const* d_in, const int* in_sizes, int n_in,
                              void* d_out, int out_size) {
    (void)in_sizes; (void)n_in; (void)out_size;
    const float* lig_feat   = (const float*)d_in[0];
    const float* rec_feat   = (const float*)d_in[1];
    const float* lig_coord  = (const float*)d_in[2];
    const float* rec_coord  = (const float*)d_in[3];
    const float* pre_rot    = (const float*)d_in[4];
    const float* trans      = (const float*)d_in[5];
    const int*   lig_counts = (const int*)d_in[6];
    const int*   rec_counts = (const int*)d_in[7];
    float* out = (float*)d_out;

    cudaFuncSetAttribute(fused_energy, cudaFuncAttributeMaxDynamicSharedMemorySize, FUSED_SMEM);

    dim3 g1(16, NB);
    fused_energy<<<g1, NTHR, FUSED_SMEM>>>(lig_feat, rec_feat, lig_coord, rec_coord,
                                           pre_rot, trans, lig_counts, rec_counts, out);
}